// round 4
// baseline (speedup 1.0000x reference)
#include <cuda_runtime.h>
#include <cuda_bf16.h>
#include <cstdint>

// ---------------------------------------------------------------------------
// Problem constants
// ---------------------------------------------------------------------------
#define BSZ  32
#define CC   1536
#define CI   768
#define HH   14
#define WW   14
#define HJ   28
#define WJ   28
#define NN   784
#define MM   196
#define MMP  224          // MM padded to a multiple of 32 (16B-aligned rows)
#define CTPG 2304

// ---------------------------------------------------------------------------
// Scratch (device globals)
// ---------------------------------------------------------------------------
__device__ __align__(16) __nv_bfloat16 g_xhT[(size_t)BSZ * NN * CC];
__device__ __align__(16) __nv_bfloat16 g_xlT[(size_t)BSZ * NN * CC];
__device__ float g_tpg [(size_t)BSZ * CTPG * NN];
__device__ __align__(16) __nv_bfloat16 g_thh[(size_t)BSZ * NN * CI];   // theta^T hi
__device__ __align__(16) __nv_bfloat16 g_thl[(size_t)BSZ * NN * CI];   // theta^T lo
__device__ float g_phi [(size_t)BSZ * CI * MM];                        // pooled phi fp32
__device__ __align__(16) __nv_bfloat16 g_phh[(size_t)BSZ * MM * CI];   // phi^T hi
__device__ __align__(16) __nv_bfloat16 g_phl[(size_t)BSZ * MM * CI];   // phi^T lo
__device__ __align__(16) __nv_bfloat16 g_gph[(size_t)BSZ * CI * MMP];  // pooled g hi (K-padded)
__device__ __align__(16) __nv_bfloat16 g_gpl[(size_t)BSZ * CI * MMP];
__device__ float g_f   [(size_t)BSZ * NN * MM];                        // logits
__device__ __align__(16) __nv_bfloat16 g_ath[(size_t)BSZ * NN * MMP];  // attn hi (K-padded)
__device__ __align__(16) __nv_bfloat16 g_atl[(size_t)BSZ * NN * MMP];
__device__ float g_y   [(size_t)BSZ * CI * NN];
__device__ __align__(16) __nv_bfloat16 g_yhT[(size_t)BSZ * NN * CI];
__device__ __align__(16) __nv_bfloat16 g_ylT[(size_t)BSZ * NN * CI];
__device__ __align__(16) __nv_bfloat16 g_whi[(size_t)CTPG * CC];
__device__ __align__(16) __nv_bfloat16 g_wlo[(size_t)CTPG * CC];
__device__ __align__(16) __nv_bfloat16 g_wWhi[(size_t)CC * CI];
__device__ __align__(16) __nv_bfloat16 g_wWlo[(size_t)CC * CI];
__device__ float g_bstk[CTPG];
__device__ float g_escale[CC];
__device__ float g_eshift[CC];

// ---------------------------------------------------------------------------
// PTX helpers (base ISA only — no 'a'-gated features; ptxas targets sm_103)
// ---------------------------------------------------------------------------
__device__ __forceinline__ uint32_t smem_u32(const void* p) {
    uint32_t a;
    asm("{ .reg .u64 t; cvta.to.shared.u64 t, %1; cvt.u32.u64 %0, t; }" : "=r"(a) : "l"(p));
    return a;
}
__device__ __forceinline__ void ldm_x4(uint32_t* r, uint32_t addr) {
    asm volatile("ldmatrix.sync.aligned.m8n8.x4.shared.b16 {%0,%1,%2,%3}, [%4];"
                 : "=r"(r[0]), "=r"(r[1]), "=r"(r[2]), "=r"(r[3]) : "r"(addr));
}
__device__ __forceinline__ void mma16816(float* d, const uint32_t* a, uint32_t b0, uint32_t b1) {
    asm volatile("mma.sync.aligned.m16n8k16.row.col.f32.bf16.bf16.f32 "
                 "{%0,%1,%2,%3}, {%4,%5,%6,%7}, {%8,%9}, {%0,%1,%2,%3};"
                 : "+f"(d[0]), "+f"(d[1]), "+f"(d[2]), "+f"(d[3])
                 : "r"(a[0]), "r"(a[1]), "r"(a[2]), "r"(a[3]), "r"(b0), "r"(b1));
}
__device__ __forceinline__ void cpa16(uint32_t dst, const void* src, int srcsz) {
    asm volatile("cp.async.cg.shared.global [%0], [%1], 16, %2;"
                 :: "r"(dst), "l"(src), "r"(srcsz));
}
#define CPA_COMMIT()  asm volatile("cp.async.commit_group;" ::: "memory")
#define CPA_WAIT(n)   asm volatile("cp.async.wait_group %0;" :: "n"(n) : "memory")

// ---------------------------------------------------------------------------
// fused joint-gather + transpose + bf16 hi/lo split:
//   x (B*4, C, 14, 14) -> xjT [b][n][c] hi/lo
// ---------------------------------------------------------------------------
__global__ void tsplitX_kernel(const float* __restrict__ x) {
    __shared__ float t[32][33];
    int b = blockIdx.z;
    int c0 = blockIdx.y * 32, n0 = blockIdx.x * 32;
    int tx = threadIdx.x, ty = threadIdx.y;
#pragma unroll
    for (int s = 0; s < 32; s += 8) {
        int c = c0 + ty + s, n = n0 + tx;
        float v = 0.f;
        if (n < NN) {
            int hj = n / WJ, wj = n % WJ;
            int vv = ((hj >= HH) ? 2 : 0) + ((wj >= WW) ? 1 : 0);
            int hl = (hj >= HH) ? hj - HH : hj;
            int wl = (wj >= WW) ? wj - WW : wj;
            v = x[(((long)(b * 4 + vv) * CC + c) * HH + hl) * WW + wl];
        }
        t[ty + s][tx] = v;
    }
    __syncthreads();
    long ob = (long)b * NN * CC;
#pragma unroll
    for (int s = 0; s < 32; s += 8) {
        int n = n0 + ty + s, c = c0 + tx;
        if (n < NN) {
            float v = t[tx][ty + s];
            __nv_bfloat16 h = __float2bfloat16(v);
            g_xhT[ob + (long)n * CC + c] = h;
            g_xlT[ob + (long)n * CC + c] = __float2bfloat16(v - __bfloat162float(h));
        }
    }
}

// ---------------------------------------------------------------------------
// generic tiled transpose + bf16 hi/lo split:  in [b][R][Cn] fp32 (batch
// stride inStride) -> hi/lo [b][Cn][R]
// ---------------------------------------------------------------------------
__global__ void tsplit_kernel(const float* __restrict__ in,
                              __nv_bfloat16* __restrict__ hi,
                              __nv_bfloat16* __restrict__ lo,
                              int R, int Cn, long inStride) {
    __shared__ float t[32][33];
    int b = blockIdx.z;
    int r0 = blockIdx.y * 32, c0 = blockIdx.x * 32;
    const float* ib = in + (long)b * inStride;
    int tx = threadIdx.x, ty = threadIdx.y;
#pragma unroll
    for (int s = 0; s < 32; s += 8) {
        int r = r0 + ty + s, c = c0 + tx;
        t[ty + s][tx] = (r < R && c < Cn) ? ib[(long)r * Cn + c] : 0.f;
    }
    __syncthreads();
    long ob = (long)b * Cn * R;
#pragma unroll
    for (int s = 0; s < 32; s += 8) {
        int c = c0 + ty + s, r = r0 + tx;
        if (c < Cn && r < R) {
            float v = t[tx][ty + s];
            __nv_bfloat16 h = __float2bfloat16(v);
            hi[ob + (long)c * R + r] = h;
            lo[ob + (long)c * R + r] = __float2bfloat16(v - __bfloat162float(h));
        }
    }
}

// ---------------------------------------------------------------------------
// weight prep
// ---------------------------------------------------------------------------
__global__ void wsplit_stack_kernel(const float* __restrict__ wt, const float* __restrict__ wp,
                                    const float* __restrict__ wg, const float* __restrict__ bt,
                                    const float* __restrict__ bp, const float* __restrict__ bg) {
    long idx = (long)blockIdx.x * blockDim.x + threadIdx.x;
    if (idx < (long)CTPG * CC) {
        int r = (int)(idx / CC), c = (int)(idx % CC);
        const float* src = (r < CI) ? wt : ((r < 2 * CI) ? wp : wg);
        int rr = (r < CI) ? r : ((r < 2 * CI) ? r - CI : r - 2 * CI);
        float v = src[(long)rr * CC + c];
        __nv_bfloat16 h = __float2bfloat16(v);
        g_whi[idx] = h;
        g_wlo[idx] = __float2bfloat16(v - __bfloat162float(h));
    }
    if (idx < CTPG) {
        int r = (int)idx;
        g_bstk[r] = (r < CI) ? bt[r] : ((r < 2 * CI) ? bp[r - CI] : bg[r - 2 * CI]);
    }
}

__global__ void wsplitW_kernel(const float* __restrict__ wW) {
    long idx = (long)blockIdx.x * blockDim.x + threadIdx.x;
    if (idx >= (long)CC * CI) return;
    float v = wW[idx];
    __nv_bfloat16 h = __float2bfloat16(v);
    g_wWhi[idx] = h;
    g_wWlo[idx] = __float2bfloat16(v - __bfloat162float(h));
}

__global__ void bnprep_kernel(const float* __restrict__ gamma, const float* __restrict__ beta,
                              const float* __restrict__ mean, const float* __restrict__ var,
                              const float* __restrict__ bW) {
    int m = blockIdx.x * blockDim.x + threadIdx.x;
    if (m < CC) {
        float s = gamma[m] * rsqrtf(var[m] + 1e-5f);
        g_escale[m] = s;
        g_eshift[m] = beta[m] - mean[m] * s + bW[m] * s;
    }
}

// ---------------------------------------------------------------------------
// 2x2 maxpool: phi part -> fp32 [c][196]; g part -> bf16 hi/lo [c][224] padded
// ---------------------------------------------------------------------------
__global__ void pool_kernel() {
    int idx = blockIdx.x * blockDim.x + threadIdx.x;
    const int totPhi = BSZ * CI * MM;
    const int totG = BSZ * CI * MMP;
    if (idx < totPhi) {
        int m = idx % MM;
        int c = (idx / MM) % CI;
        int b = idx / (MM * CI);
        int hm = m / 14, wm = m % 14;
        const float* src = g_tpg + ((long)b * CTPG + CI + c) * NN;
        int base = (2 * hm) * WJ + 2 * wm;
        g_phi[idx] = fmaxf(fmaxf(src[base], src[base + 1]),
                           fmaxf(src[base + WJ], src[base + WJ + 1]));
    } else if (idx < totPhi + totG) {
        int r = idx - totPhi;
        int j = r % MMP;
        int c = (r / MMP) % CI;
        int b = r / (MMP * CI);
        float v = 0.f;
        if (j < MM) {
            int hm = j / 14, wm = j % 14;
            const float* src = g_tpg + ((long)b * CTPG + 2 * CI + c) * NN;
            int base = (2 * hm) * WJ + 2 * wm;
            v = fmaxf(fmaxf(src[base], src[base + 1]),
                      fmaxf(src[base + WJ], src[base + WJ + 1]));
        }
        __nv_bfloat16 h = __float2bfloat16(v);
        g_gph[r] = h;
        g_gpl[r] = (j < MM) ? __float2bfloat16(v - __bfloat162float(h)) : __nv_bfloat16(0.f);
    }
}

// ---------------------------------------------------------------------------
// row softmax over MM=196; writes attn hi/lo bf16 padded [n][224]
// ---------------------------------------------------------------------------
__global__ void softmax_kernel() {
    int warp = (blockIdx.x * blockDim.x + threadIdx.x) >> 5;
    int lane = threadIdx.x & 31;
    if (warp >= BSZ * NN) return;
    const float* row = g_f + (long)warp * MM;
    __nv_bfloat16* oh = g_ath + (long)warp * MMP;
    __nv_bfloat16* ol = g_atl + (long)warp * MMP;
    float vals[7];
    float mx = -1e30f;
#pragma unroll
    for (int s = 0; s < 7; s++) {
        int i = lane + s * 32;
        vals[s] = (i < MM) ? row[i] : -1e30f;
        mx = fmaxf(mx, vals[s]);
    }
#pragma unroll
    for (int o = 16; o; o >>= 1) mx = fmaxf(mx, __shfl_xor_sync(0xffffffffu, mx, o));
    float sum = 0.f;
#pragma unroll
    for (int s = 0; s < 7; s++) {
        int i = lane + s * 32;
        vals[s] = (i < MM) ? __expf(vals[s] - mx) : 0.f;
        sum += vals[s];
    }
#pragma unroll
    for (int o = 16; o; o >>= 1) sum += __shfl_xor_sync(0xffffffffu, sum, o);
    float inv = 1.f / sum;
#pragma unroll
    for (int s = 0; s < 7; s++) {
        int i = lane + s * 32;   // covers 0..223 == MMP exactly
        float v = vals[s] * inv;
        __nv_bfloat16 h = __float2bfloat16(v);
        oh[i] = h;
        ol[i] = __float2bfloat16(v - __bfloat162float(h));
    }
}

// ---------------------------------------------------------------------------
// bf16-split tensor GEMM (mma.sync m16n8k16), 256x128 CTA tile, 512 threads,
// 3-stage cp.async pipeline. D[m][n] = sum_k A[m][k]*B[n][k] over 3 passes
// (Ahi,Bhi),(Alo,Bhi),(Ahi,Blo), fp32 accum.
//   EPI 0: plain store   EPI 1: +g_bstk[m]   EPI 2: BN-fold + residual from x
// ---------------------------------------------------------------------------
#define AST (256 * 40)     // bf16 elems per A stage
#define BST (128 * 40)
#define SMEM_BYTES ((3 * (AST + BST)) * 2)

template <int EPI>
__global__ void __launch_bounds__(512, 1)
mma256_kernel(const __nv_bfloat16* __restrict__ Ahi, const __nv_bfloat16* __restrict__ Alo,
              const __nv_bfloat16* __restrict__ Bhi, const __nv_bfloat16* __restrict__ Blo,
              float* __restrict__ Cp, int K, int MV, int NB,
              long strideA, long strideB, int ldC, long sC,
              const float* __restrict__ xres) {
    extern __shared__ __align__(16) __nv_bfloat16 smem[];
    __nv_bfloat16* sAb = smem;                 // [3][256][40]
    __nv_bfloat16* sBb = smem + 3 * AST;       // [3][128][40]

    const int tid = threadIdx.x;
    const int lane = tid & 31;
    const int wid = tid >> 5;
    const int wm = wid & 3;          // 4 M-warps -> 64 rows each
    const int wn = wid >> 2;         // 4 N-warps -> 32 cols each
    const int m0 = blockIdx.y * 256;
    const int n0 = blockIdx.x * 128;
    const int b  = blockIdx.z;

    const int NK = K / 32;
    const int total = 3 * NK;
    const __nv_bfloat16* A0 = Ahi + (long)b * strideA + (long)m0 * K;
    const __nv_bfloat16* A1 = Alo + (long)b * strideA + (long)m0 * K;
    const __nv_bfloat16* B0 = Bhi + (long)b * strideB;
    const __nv_bfloat16* B1 = Blo + (long)b * strideB;
    const __nv_bfloat16* Asrc[3] = {A0, A1, A0};
    const __nv_bfloat16* Bsrc[3] = {B0, B0, B1};

    float acc[4][4][4];
#pragma unroll
    for (int i = 0; i < 4; i++)
#pragma unroll
        for (int j = 0; j < 4; j++)
#pragma unroll
            for (int r = 0; r < 4; r++) acc[i][j][r] = 0.f;

    // A: 256 rows x 4 segs = 1024 slots (2/thread); B: 128 x 4 = 512 (1/thread)
    auto loadChunk = [&](int g, int buf) {
        int p = g / NK;
        int kc = (g - p * NK) * 32;
        const __nv_bfloat16* Ab = Asrc[p] + kc;
        const __nv_bfloat16* Bb = Bsrc[p] + kc;
        __nv_bfloat16* dA = sAb + buf * AST;
        __nv_bfloat16* dB = sBb + buf * BST;
#pragma unroll
        for (int i = 0; i < 2; i++) {
            int idx = tid + i * 512;
            int row = idx >> 2, seg = idx & 3;
            int ok = (m0 + row) < MV;
            cpa16(smem_u32(dA + row * 40 + seg * 8),
                  Ab + (long)row * K + seg * 8, ok ? 16 : 0);
        }
        {
            int row = tid >> 2, seg = tid & 3;
            int ok = (n0 + row) < NB;
            cpa16(smem_u32(dB + row * 40 + seg * 8),
                  Bb + (long)(ok ? (n0 + row) : 0) * K + seg * 8, ok ? 16 : 0);
        }
    };

    loadChunk(0, 0); CPA_COMMIT();
    loadChunk(1, 1); CPA_COMMIT();

    for (int g = 0; g < total; g++) {
        int buf = g - (g / 3) * 3;
        if (g + 1 < total) { CPA_WAIT(1); } else { CPA_WAIT(0); }
        __syncthreads();
        if (g + 2 < total) {
            int nbuf = (g + 2) - ((g + 2) / 3) * 3;
            loadChunk(g + 2, nbuf);
            CPA_COMMIT();
        }
        const __nv_bfloat16* sA = sAb + buf * AST;
        const __nv_bfloat16* sB = sBb + buf * BST;
#pragma unroll
        for (int ks = 0; ks < 2; ks++) {
            uint32_t a[4][4];
#pragma unroll
            for (int mi = 0; mi < 4; mi++) {
                int mr = wm * 64 + mi * 16 + ((lane >> 3) & 1) * 8 + (lane & 7);
                int kk = ks * 16 + (lane >> 4) * 8;
                ldm_x4(a[mi], smem_u32(sA + mr * 40 + kk));
            }
            uint32_t bf[2][4];
#pragma unroll
            for (int ni = 0; ni < 2; ni++) {
                int nr = wn * 32 + ni * 16 + (lane >> 4) * 8 + (lane & 7);
                int kk = ks * 16 + ((lane >> 3) & 1) * 8;
                ldm_x4(bf[ni], smem_u32(sB + nr * 40 + kk));
            }
#pragma unroll
            for (int mi = 0; mi < 4; mi++)
#pragma unroll
                for (int nj = 0; nj < 4; nj++)
                    mma16816(acc[mi][nj], a[mi],
                             bf[nj >> 1][(nj & 1) * 2], bf[nj >> 1][(nj & 1) * 2 + 1]);
        }
        __syncthreads();
    }

    // epilogue
    const int mbase = m0 + wm * 64;
    const int nbase = n0 + wn * 32;
    float* Cb = Cp + (long)b * sC;
#pragma unroll
    for (int mi = 0; mi < 4; mi++) {
        int mr0 = mbase + mi * 16 + (lane >> 2);
        int mr1 = mr0 + 8;
        bool ok0 = mr0 < MV, ok1 = mr1 < MV;
        float es0 = 1.f, eh0 = 0.f, es1 = 1.f, eh1 = 0.f;
        if (EPI == 1) { if (ok0) eh0 = g_bstk[mr0]; if (ok1) eh1 = g_bstk[mr1]; }
        if (EPI == 2) {
            if (ok0) { es0 = g_escale[mr0]; eh0 = g_eshift[mr0]; }
            if (ok1) { es1 = g_escale[mr1]; eh1 = g_eshift[mr1]; }
        }
#pragma unroll
        for (int nj = 0; nj < 4; nj++) {
            int n = nbase + nj * 8 + (lane & 3) * 2;
            if (n >= NB) continue;
            float2 v0 = make_float2(acc[mi][nj][0], acc[mi][nj][1]);
            float2 v1 = make_float2(acc[mi][nj][2], acc[mi][nj][3]);
            if (EPI == 2) {
                // residual = joint(x)[b][m][n], gathered inline
                int hj = n / WJ, wj0 = n - hj * WJ;
#pragma unroll
                for (int e = 0; e < 2; e++) {
                    int wj = wj0 + e;
                    int vv = ((hj >= HH) ? 2 : 0) + ((wj >= WW) ? 1 : 0);
                    int hl = (hj >= HH) ? hj - HH : hj;
                    int wl = (wj >= WW) ? wj - WW : wj;
                    long base = (((long)(b * 4 + vv) * CC) * HH + hl) * WW + wl;
                    float r0 = ok0 ? xres[base + (long)mr0 * HH * WW] : 0.f;
                    float r1 = ok1 ? xres[base + (long)mr1 * HH * WW] : 0.f;
                    if (e == 0) { v0.x = v0.x * es0 + eh0 + r0; v1.x = v1.x * es1 + eh1 + r1; }
                    else        { v0.y = v0.y * es0 + eh0 + r0; v1.y = v1.y * es1 + eh1 + r1; }
                }
            } else {
                v0.x = v0.x * es0 + eh0; v0.y = v0.y * es0 + eh0;
                v1.x = v1.x * es1 + eh1; v1.y = v1.y * es1 + eh1;
            }
            if (ok0) *(float2*)(Cb + (long)mr0 * ldC + n) = v0;
            if (ok1) *(float2*)(Cb + (long)mr1 * ldC + n) = v1;
        }
    }
}

// ---------------------------------------------------------------------------
// Launch
// ---------------------------------------------------------------------------
extern "C" void kernel_launch(void* const* d_in, const int* in_sizes, int n_in,
                              void* d_out, int out_size) {
    const float* x     = (const float*)d_in[0];
    const float* wt    = (const float*)d_in[1];
    const float* bt    = (const float*)d_in[2];
    const float* wp    = (const float*)d_in[3];
    const float* bp    = (const float*)d_in[4];
    const float* wg    = (const float*)d_in[5];
    const float* bg    = (const float*)d_in[6];
    const float* wW    = (const float*)d_in[7];
    const float* bW    = (const float*)d_in[8];
    const float* gamma = (const float*)d_in[9];
    const float* beta  = (const float*)d_in[10];
    const float* mean  = (const float*)d_in[11];
    const float* var   = (const float*)d_in[12];
    float* out = (float*)d_out;

    float *p_tpg, *p_phi, *p_f, *p_y;
    __nv_bfloat16 *p_xhT, *p_xlT, *p_thh, *p_thl, *p_phh, *p_phl;
    __nv_bfloat16 *p_gph, *p_gpl, *p_ath, *p_atl, *p_yhT, *p_ylT;
    __nv_bfloat16 *p_whi, *p_wlo, *p_wWhi, *p_wWlo;
    cudaGetSymbolAddress((void**)&p_tpg, g_tpg);
    cudaGetSymbolAddress((void**)&p_phi, g_phi);
    cudaGetSymbolAddress((void**)&p_f, g_f);
    cudaGetSymbolAddress((void**)&p_y, g_y);
    cudaGetSymbolAddress((void**)&p_xhT, g_xhT);
    cudaGetSymbolAddress((void**)&p_xlT, g_xlT);
    cudaGetSymbolAddress((void**)&p_thh, g_thh);
    cudaGetSymbolAddress((void**)&p_thl, g_thl);
    cudaGetSymbolAddress((void**)&p_phh, g_phh);
    cudaGetSymbolAddress((void**)&p_phl, g_phl);
    cudaGetSymbolAddress((void**)&p_gph, g_gph);
    cudaGetSymbolAddress((void**)&p_gpl, g_gpl);
    cudaGetSymbolAddress((void**)&p_ath, g_ath);
    cudaGetSymbolAddress((void**)&p_atl, g_atl);
    cudaGetSymbolAddress((void**)&p_yhT, g_yhT);
    cudaGetSymbolAddress((void**)&p_ylT, g_ylT);
    cudaGetSymbolAddress((void**)&p_whi, g_whi);
    cudaGetSymbolAddress((void**)&p_wlo, g_wlo);
    cudaGetSymbolAddress((void**)&p_wWhi, g_wWhi);
    cudaGetSymbolAddress((void**)&p_wWlo, g_wWlo);

    cudaFuncSetAttribute(mma256_kernel<0>, cudaFuncAttributeMaxDynamicSharedMemorySize, SMEM_BYTES);
    cudaFuncSetAttribute(mma256_kernel<1>, cudaFuncAttributeMaxDynamicSharedMemorySize, SMEM_BYTES);
    cudaFuncSetAttribute(mma256_kernel<2>, cudaFuncAttributeMaxDynamicSharedMemorySize, SMEM_BYTES);

    // 1. weight prep
    {
        long total = (long)CTPG * CC;
        wsplit_stack_kernel<<<(unsigned)((total + 255) / 256), 256>>>(wt, wp, wg, bt, bp, bg);
        wsplitW_kernel<<<(unsigned)(((long)CC * CI + 255) / 256), 256>>>(wW);
        bnprep_kernel<<<(CC + 255) / 256, 256>>>(gamma, beta, mean, var, bW);
    }
    // 2. fused joint + transpose + split: x -> xjT hi/lo
    {
        dim3 grid((NN + 31) / 32, CC / 32, BSZ);
        tsplitX_kernel<<<grid, dim3(32, 8)>>>(x);
    }
    // 3. stacked theta|phi|g conv: tpg[b] = Wstk * xj[b] + bstk
    {
        dim3 grid(NN / 112 /*7*/, CTPG / 256, BSZ);
        mma256_kernel<1><<<dim3(7, CTPG / 256, BSZ), 512, SMEM_BYTES>>>(
            p_whi, p_wlo, p_xhT, p_xlT, p_tpg, CC, CTPG, NN,
            0L, (long)NN * CC, NN, (long)CTPG * NN, nullptr);
        (void)grid;
    }
    // 4. pool: phi fp32 + g hi/lo padded
    {
        int total = BSZ * CI * (MM + MMP);
        pool_kernel<<<(total + 255) / 256, 256>>>();
    }
    // 5. theta slice of tpg -> theta^T hi/lo
    {
        dim3 grid((NN + 31) / 32, CI / 32, BSZ);
        tsplit_kernel<<<grid, dim3(32, 8)>>>(p_tpg, p_thh, p_thl, CI, NN, (long)CTPG * NN);
    }
    // 6. phi -> phi^T hi/lo
    {
        dim3 grid((MM + 31) / 32, CI / 32, BSZ);
        tsplit_kernel<<<grid, dim3(32, 8)>>>(p_phi, p_phh, p_phl, CI, MM, (long)CI * MM);
    }
    // 7. f[b] (784x196) = thetaT (784x768) @ phiT^T  (tensor)
    {
        mma256_kernel<0><<<dim3(2, (NN + 255) / 256, BSZ), 512, SMEM_BYTES>>>(
            p_thh, p_thl, p_phh, p_phl, p_f, CI, NN, MM,
            (long)NN * CI, (long)MM * CI, MM, (long)NN * MM, nullptr);
    }
    // 8. softmax -> attn hi/lo padded
    {
        int rows = BSZ * NN;
        softmax_kernel<<<(rows * 32 + 255) / 256, 256>>>();
    }
    // 9. y[b] (768x784) = g (768x224p) @ attn^T  (tensor)
    {
        mma256_kernel<0><<<dim3(7, CI / 256, BSZ), 512, SMEM_BYTES>>>(
            p_gph, p_gpl, p_ath, p_atl, p_y, MMP, CI, NN,
            (long)CI * MMP, (long)NN * MMP, NN, (long)CI * NN, nullptr);
    }
    // 10. y -> y^T hi/lo
    {
        dim3 grid((NN + 31) / 32, CI / 32, BSZ);
        tsplit_kernel<<<grid, dim3(32, 8)>>>(p_y, p_yhT, p_ylT, CI, NN, (long)CI * NN);
    }
    // 11. W conv + BN + residual (inline joint gather) -> out
    {
        mma256_kernel<2><<<dim3(7, CC / 256, BSZ), 512, SMEM_BYTES>>>(
            p_wWhi, p_wWlo, p_yhT, p_ylT, out, CI, CC, NN,
            0L, (long)NN * CI, NN, (long)CC * NN, x);
    }
}

// round 5
// speedup vs baseline: 1.2163x; 1.2163x over previous
#include <cuda_runtime.h>
#include <cuda_bf16.h>
#include <cstdint>

// ---------------------------------------------------------------------------
// Problem constants
// ---------------------------------------------------------------------------
#define BSZ  32
#define CC   1536
#define CI   768
#define HH   14
#define WW   14
#define HJ   28
#define WJ   28
#define NN   784
#define MM   196
#define MMP  224          // MM padded to multiple of 32
#define CTPG 2304

// ---------------------------------------------------------------------------
// Scratch (device globals)
// ---------------------------------------------------------------------------
__device__ __align__(16) __nv_bfloat16 g_xhT[(size_t)BSZ * NN * CC];
__device__ __align__(16) __nv_bfloat16 g_xlT[(size_t)BSZ * NN * CC];
__device__ float g_tpg [(size_t)BSZ * CTPG * NN];
__device__ __align__(16) __nv_bfloat16 g_thh[(size_t)BSZ * NN * CI];
__device__ __align__(16) __nv_bfloat16 g_thl[(size_t)BSZ * NN * CI];
__device__ float g_phi [(size_t)BSZ * CI * MM];
__device__ __align__(16) __nv_bfloat16 g_phh[(size_t)BSZ * MM * CI];
__device__ __align__(16) __nv_bfloat16 g_phl[(size_t)BSZ * MM * CI];
__device__ __align__(16) __nv_bfloat16 g_gph[(size_t)BSZ * CI * MMP];
__device__ __align__(16) __nv_bfloat16 g_gpl[(size_t)BSZ * CI * MMP];
__device__ float g_f   [(size_t)BSZ * NN * MM];
__device__ __align__(16) __nv_bfloat16 g_ath[(size_t)BSZ * NN * MMP];
__device__ __align__(16) __nv_bfloat16 g_atl[(size_t)BSZ * NN * MMP];
__device__ float g_y   [(size_t)BSZ * CI * NN];
__device__ __align__(16) __nv_bfloat16 g_yhT[(size_t)BSZ * NN * CI];
__device__ __align__(16) __nv_bfloat16 g_ylT[(size_t)BSZ * NN * CI];
__device__ __align__(16) __nv_bfloat16 g_whi[(size_t)CTPG * CC];
__device__ __align__(16) __nv_bfloat16 g_wlo[(size_t)CTPG * CC];
__device__ __align__(16) __nv_bfloat16 g_wWhi[(size_t)CC * CI];
__device__ __align__(16) __nv_bfloat16 g_wWlo[(size_t)CC * CI];
__device__ float g_bstk[CTPG];
__device__ float g_escale[CC];
__device__ float g_eshift[CC];

// ---------------------------------------------------------------------------
// PTX helpers (base ISA only)
// ---------------------------------------------------------------------------
__device__ __forceinline__ uint32_t smem_u32(const void* p) {
    uint32_t a;
    asm("{ .reg .u64 t; cvta.to.shared.u64 t, %1; cvt.u32.u64 %0, t; }" : "=r"(a) : "l"(p));
    return a;
}
__device__ __forceinline__ void ldm_x4(uint32_t* r, uint32_t addr) {
    asm volatile("ldmatrix.sync.aligned.m8n8.x4.shared.b16 {%0,%1,%2,%3}, [%4];"
                 : "=r"(r[0]), "=r"(r[1]), "=r"(r[2]), "=r"(r[3]) : "r"(addr));
}
__device__ __forceinline__ void mma16816(float* d, const uint32_t* a, uint32_t b0, uint32_t b1) {
    asm volatile("mma.sync.aligned.m16n8k16.row.col.f32.bf16.bf16.f32 "
                 "{%0,%1,%2,%3}, {%4,%5,%6,%7}, {%8,%9}, {%0,%1,%2,%3};"
                 : "+f"(d[0]), "+f"(d[1]), "+f"(d[2]), "+f"(d[3])
                 : "r"(a[0]), "r"(a[1]), "r"(a[2]), "r"(a[3]), "r"(b0), "r"(b1));
}
__device__ __forceinline__ void cpa16(uint32_t dst, const void* src, int srcsz) {
    asm volatile("cp.async.cg.shared.global [%0], [%1], 16, %2;"
                 :: "r"(dst), "l"(src), "r"(srcsz));
}
#define CPA_COMMIT()  asm volatile("cp.async.commit_group;" ::: "memory")
#define CPA_WAIT(n)   asm volatile("cp.async.wait_group %0;" :: "n"(n) : "memory")

// ---------------------------------------------------------------------------
// fused joint-gather + transpose + bf16 hi/lo split: x -> xjT [b][n][c]
// ---------------------------------------------------------------------------
__global__ void tsplitX_kernel(const float* __restrict__ x) {
    __shared__ float t[32][33];
    int b = blockIdx.z;
    int c0 = blockIdx.y * 32, n0 = blockIdx.x * 32;
    int tx = threadIdx.x, ty = threadIdx.y;
#pragma unroll
    for (int s = 0; s < 32; s += 8) {
        int c = c0 + ty + s, n = n0 + tx;
        float v = 0.f;
        if (n < NN) {
            int hj = n / WJ, wj = n % WJ;
            int vv = ((hj >= HH) ? 2 : 0) + ((wj >= WW) ? 1 : 0);
            int hl = (hj >= HH) ? hj - HH : hj;
            int wl = (wj >= WW) ? wj - WW : wj;
            v = x[(((long)(b * 4 + vv) * CC + c) * HH + hl) * WW + wl];
        }
        t[ty + s][tx] = v;
    }
    __syncthreads();
    long ob = (long)b * NN * CC;
#pragma unroll
    for (int s = 0; s < 32; s += 8) {
        int n = n0 + ty + s, c = c0 + tx;
        if (n < NN) {
            float v = t[tx][ty + s];
            __nv_bfloat16 h = __float2bfloat16(v);
            g_xhT[ob + (long)n * CC + c] = h;
            g_xlT[ob + (long)n * CC + c] = __float2bfloat16(v - __bfloat162float(h));
        }
    }
}

// ---------------------------------------------------------------------------
// generic tiled transpose + bf16 hi/lo split
// ---------------------------------------------------------------------------
__global__ void tsplit_kernel(const float* __restrict__ in,
                              __nv_bfloat16* __restrict__ hi,
                              __nv_bfloat16* __restrict__ lo,
                              int R, int Cn, long inStride) {
    __shared__ float t[32][33];
    int b = blockIdx.z;
    int r0 = blockIdx.y * 32, c0 = blockIdx.x * 32;
    const float* ib = in + (long)b * inStride;
    int tx = threadIdx.x, ty = threadIdx.y;
#pragma unroll
    for (int s = 0; s < 32; s += 8) {
        int r = r0 + ty + s, c = c0 + tx;
        t[ty + s][tx] = (r < R && c < Cn) ? ib[(long)r * Cn + c] : 0.f;
    }
    __syncthreads();
    long ob = (long)b * Cn * R;
#pragma unroll
    for (int s = 0; s < 32; s += 8) {
        int c = c0 + ty + s, r = r0 + tx;
        if (c < Cn && r < R) {
            float v = t[tx][ty + s];
            __nv_bfloat16 h = __float2bfloat16(v);
            hi[ob + (long)c * R + r] = h;
            lo[ob + (long)c * R + r] = __float2bfloat16(v - __bfloat162float(h));
        }
    }
}

// ---------------------------------------------------------------------------
// weight prep
// ---------------------------------------------------------------------------
__global__ void wsplit_stack_kernel(const float* __restrict__ wt, const float* __restrict__ wp,
                                    const float* __restrict__ wg, const float* __restrict__ bt,
                                    const float* __restrict__ bp, const float* __restrict__ bg) {
    long idx = (long)blockIdx.x * blockDim.x + threadIdx.x;
    if (idx < (long)CTPG * CC) {
        int r = (int)(idx / CC), c = (int)(idx % CC);
        const float* src = (r < CI) ? wt : ((r < 2 * CI) ? wp : wg);
        int rr = (r < CI) ? r : ((r < 2 * CI) ? r - CI : r - 2 * CI);
        float v = src[(long)rr * CC + c];
        __nv_bfloat16 h = __float2bfloat16(v);
        g_whi[idx] = h;
        g_wlo[idx] = __float2bfloat16(v - __bfloat162float(h));
    }
    if (idx < CTPG) {
        int r = (int)idx;
        g_bstk[r] = (r < CI) ? bt[r] : ((r < 2 * CI) ? bp[r - CI] : bg[r - 2 * CI]);
    }
}

__global__ void wsplitW_kernel(const float* __restrict__ wW) {
    long idx = (long)blockIdx.x * blockDim.x + threadIdx.x;
    if (idx >= (long)CC * CI) return;
    float v = wW[idx];
    __nv_bfloat16 h = __float2bfloat16(v);
    g_wWhi[idx] = h;
    g_wWlo[idx] = __float2bfloat16(v - __bfloat162float(h));
}

__global__ void bnprep_kernel(const float* __restrict__ gamma, const float* __restrict__ beta,
                              const float* __restrict__ mean, const float* __restrict__ var,
                              const float* __restrict__ bW) {
    int m = blockIdx.x * blockDim.x + threadIdx.x;
    if (m < CC) {
        float s = gamma[m] * rsqrtf(var[m] + 1e-5f);
        g_escale[m] = s;
        g_eshift[m] = beta[m] - mean[m] * s + bW[m] * s;
    }
}

// ---------------------------------------------------------------------------
// 2x2 maxpool: phi -> fp32 [c][196]; g -> bf16 hi/lo [c][224] padded
// ---------------------------------------------------------------------------
__global__ void pool_kernel() {
    int idx = blockIdx.x * blockDim.x + threadIdx.x;
    const int totPhi = BSZ * CI * MM;
    const int totG = BSZ * CI * MMP;
    if (idx < totPhi) {
        int m = idx % MM;
        int c = (idx / MM) % CI;
        int b = idx / (MM * CI);
        int hm = m / 14, wm = m % 14;
        const float* src = g_tpg + ((long)b * CTPG + CI + c) * NN;
        int base = (2 * hm) * WJ + 2 * wm;
        g_phi[idx] = fmaxf(fmaxf(src[base], src[base + 1]),
                           fmaxf(src[base + WJ], src[base + WJ + 1]));
    } else if (idx < totPhi + totG) {
        int r = idx - totPhi;
        int j = r % MMP;
        int c = (r / MMP) % CI;
        int b = r / (MMP * CI);
        float v = 0.f;
        if (j < MM) {
            int hm = j / 14, wm = j % 14;
            const float* src = g_tpg + ((long)b * CTPG + 2 * CI + c) * NN;
            int base = (2 * hm) * WJ + 2 * wm;
            v = fmaxf(fmaxf(src[base], src[base + 1]),
                      fmaxf(src[base + WJ], src[base + WJ + 1]));
        }
        __nv_bfloat16 h = __float2bfloat16(v);
        g_gph[r] = h;
        g_gpl[r] = (j < MM) ? __float2bfloat16(v - __bfloat162float(h)) : __nv_bfloat16(0.f);
    }
}

// ---------------------------------------------------------------------------
// row softmax over MM=196 -> attn hi/lo bf16 padded [n][224]
// ---------------------------------------------------------------------------
__global__ void softmax_kernel() {
    int warp = (blockIdx.x * blockDim.x + threadIdx.x) >> 5;
    int lane = threadIdx.x & 31;
    if (warp >= BSZ * NN) return;
    const float* row = g_f + (long)warp * MM;
    __nv_bfloat16* oh = g_ath + (long)warp * MMP;
    __nv_bfloat16* ol = g_atl + (long)warp * MMP;
    float vals[7];
    float mx = -1e30f;
#pragma unroll
    for (int s = 0; s < 7; s++) {
        int i = lane + s * 32;
        vals[s] = (i < MM) ? row[i] : -1e30f;
        mx = fmaxf(mx, vals[s]);
    }
#pragma unroll
    for (int o = 16; o; o >>= 1) mx = fmaxf(mx, __shfl_xor_sync(0xffffffffu, mx, o));
    float sum = 0.f;
#pragma unroll
    for (int s = 0; s < 7; s++) {
        int i = lane + s * 32;
        vals[s] = (i < MM) ? __expf(vals[s] - mx) : 0.f;
        sum += vals[s];
    }
#pragma unroll
    for (int o = 16; o; o >>= 1) sum += __shfl_xor_sync(0xffffffffu, sum, o);
    float inv = 1.f / sum;
#pragma unroll
    for (int s = 0; s < 7; s++) {
        int i = lane + s * 32;   // 0..223 == MMP
        float v = vals[s] * inv;
        __nv_bfloat16 h = __float2bfloat16(v);
        oh[i] = h;
        ol[i] = __float2bfloat16(v - __bfloat162float(h));
    }
}

// ---------------------------------------------------------------------------
// bf16-split tensor GEMM (mma.sync m16n8k16): 128x128 CTA tile, 256 threads,
// 2 CTAs/SM, 2-stage cp.async pipeline (proven R3 config).
// D[m][n] = sum_k A[m][k]*B[n][k], 3 passes (Ahi,Bhi),(Alo,Bhi),(Ahi,Blo).
//   EPI 0: plain   EPI 1: +g_bstk[m]   EPI 2: BN-fold + residual joint(x)
// ---------------------------------------------------------------------------
template <int EPI>
__global__ void __launch_bounds__(256, 2)
mma128_kernel(const __nv_bfloat16* __restrict__ Ahi, const __nv_bfloat16* __restrict__ Alo,
              const __nv_bfloat16* __restrict__ Bhi, const __nv_bfloat16* __restrict__ Blo,
              float* __restrict__ Cp, int K, int MV, int NB,
              long strideA, long strideB, int ldC, long sC,
              const float* __restrict__ xres) {
    __shared__ __nv_bfloat16 sA[2][128][40];
    __shared__ __nv_bfloat16 sB[2][128][40];

    const int tid = threadIdx.x;
    const int lane = tid & 31;
    const int wid = tid >> 5;
    const int wm = wid & 1;          // 2 M-warps -> 64 rows
    const int wn = wid >> 1;         // 4 N-warps -> 32 cols
    const int m0 = blockIdx.y * 128;
    const int n0 = blockIdx.x * 128;
    const int b  = blockIdx.z;

    const int NK = K / 32;
    const int total = 3 * NK;
    const __nv_bfloat16* A0 = Ahi + (long)b * strideA + (long)m0 * K;
    const __nv_bfloat16* A1 = Alo + (long)b * strideA + (long)m0 * K;
    const __nv_bfloat16* B0 = Bhi + (long)b * strideB;
    const __nv_bfloat16* B1 = Blo + (long)b * strideB;
    const __nv_bfloat16* Asrc[3] = {A0, A1, A0};
    const __nv_bfloat16* Bsrc[3] = {B0, B0, B1};

    float acc[4][4][4];
#pragma unroll
    for (int i = 0; i < 4; i++)
#pragma unroll
        for (int j = 0; j < 4; j++)
#pragma unroll
            for (int r = 0; r < 4; r++) acc[i][j][r] = 0.f;

    auto loadChunk = [&](int g, int buf) {
        int p = g / NK;
        int kc = (g - p * NK) * 32;
        const __nv_bfloat16* Ab = Asrc[p] + kc;
        const __nv_bfloat16* Bb = Bsrc[p] + kc;
#pragma unroll
        for (int i = 0; i < 2; i++) {
            int idx = tid + i * 256;
            int row = idx >> 2, seg = idx & 3;
            int okA = (m0 + row) < MV;
            cpa16(smem_u32(&sA[buf][row][seg * 8]),
                  Ab + (long)row * K + seg * 8, okA ? 16 : 0);
            int okB = (n0 + row) < NB;
            cpa16(smem_u32(&sB[buf][row][seg * 8]),
                  Bb + (long)(okB ? (n0 + row) : 0) * K + seg * 8, okB ? 16 : 0);
        }
    };

    loadChunk(0, 0);
    CPA_COMMIT();

    for (int g = 0; g < total; g++) {
        int buf = g & 1;
        if (g + 1 < total) {
            loadChunk(g + 1, buf ^ 1);
            CPA_COMMIT();
            CPA_WAIT(1);
        } else {
            CPA_WAIT(0);
        }
        __syncthreads();

#pragma unroll
        for (int ks = 0; ks < 2; ks++) {
            uint32_t a[4][4];
#pragma unroll
            for (int mi = 0; mi < 4; mi++) {
                int mr = wm * 64 + mi * 16 + ((lane >> 3) & 1) * 8 + (lane & 7);
                int kk = ks * 16 + (lane >> 4) * 8;
                ldm_x4(a[mi], smem_u32(&sA[buf][mr][kk]));
            }
            uint32_t bf[2][4];
#pragma unroll
            for (int ni = 0; ni < 2; ni++) {
                int nr = wn * 32 + ni * 16 + (lane >> 4) * 8 + (lane & 7);
                int kk = ks * 16 + ((lane >> 3) & 1) * 8;
                ldm_x4(bf[ni], smem_u32(&sB[buf][nr][kk]));
            }
#pragma unroll
            for (int mi = 0; mi < 4; mi++)
#pragma unroll
                for (int nj = 0; nj < 4; nj++)
                    mma16816(acc[mi][nj], a[mi],
                             bf[nj >> 1][(nj & 1) * 2], bf[nj >> 1][(nj & 1) * 2 + 1]);
        }
        __syncthreads();
    }

    // epilogue
    const int mbase = m0 + wm * 64;
    const int nbase = n0 + wn * 32;
    float* Cb = Cp + (long)b * sC;
#pragma unroll
    for (int mi = 0; mi < 4; mi++) {
        int mr0 = mbase + mi * 16 + (lane >> 2);
        int mr1 = mr0 + 8;
        bool ok0 = mr0 < MV, ok1 = mr1 < MV;
        float es0 = 1.f, eh0 = 0.f, es1 = 1.f, eh1 = 0.f;
        if (EPI == 1) { if (ok0) eh0 = g_bstk[mr0]; if (ok1) eh1 = g_bstk[mr1]; }
        if (EPI == 2) {
            if (ok0) { es0 = g_escale[mr0]; eh0 = g_eshift[mr0]; }
            if (ok1) { es1 = g_escale[mr1]; eh1 = g_eshift[mr1]; }
        }
#pragma unroll
        for (int nj = 0; nj < 4; nj++) {
            int n = nbase + nj * 8 + (lane & 3) * 2;
            if (n >= NB) continue;
            float2 v0 = make_float2(acc[mi][nj][0], acc[mi][nj][1]);
            float2 v1 = make_float2(acc[mi][nj][2], acc[mi][nj][3]);
            if (EPI == 2) {
                int hj = n / WJ, wj0 = n - hj * WJ;
#pragma unroll
                for (int e = 0; e < 2; e++) {
                    int wj = wj0 + e;
                    int vv = ((hj >= HH) ? 2 : 0) + ((wj >= WW) ? 1 : 0);
                    int hl = (hj >= HH) ? hj - HH : hj;
                    int wl = (wj >= WW) ? wj - WW : wj;
                    long base = (((long)(b * 4 + vv) * CC) * HH + hl) * WW + wl;
                    float r0 = ok0 ? xres[base + (long)mr0 * HH * WW] : 0.f;
                    float r1 = ok1 ? xres[base + (long)mr1 * HH * WW] : 0.f;
                    if (e == 0) { v0.x = v0.x * es0 + eh0 + r0; v1.x = v1.x * es1 + eh1 + r1; }
                    else        { v0.y = v0.y * es0 + eh0 + r0; v1.y = v1.y * es1 + eh1 + r1; }
                }
            } else {
                v0.x = v0.x * es0 + eh0; v0.y = v0.y * es0 + eh0;
                v1.x = v1.x * es1 + eh1; v1.y = v1.y * es1 + eh1;
            }
            if (ok0) *(float2*)(Cb + (long)mr0 * ldC + n) = v0;
            if (ok1) *(float2*)(Cb + (long)mr1 * ldC + n) = v1;
        }
    }
}

// ---------------------------------------------------------------------------
// Launch
// ---------------------------------------------------------------------------
extern "C" void kernel_launch(void* const* d_in, const int* in_sizes, int n_in,
                              void* d_out, int out_size) {
    const float* x     = (const float*)d_in[0];
    const float* wt    = (const float*)d_in[1];
    const float* bt    = (const float*)d_in[2];
    const float* wp    = (const float*)d_in[3];
    const float* bp    = (const float*)d_in[4];
    const float* wg    = (const float*)d_in[5];
    const float* bg    = (const float*)d_in[6];
    const float* wW    = (const float*)d_in[7];
    const float* bW    = (const float*)d_in[8];
    const float* gamma = (const float*)d_in[9];
    const float* beta  = (const float*)d_in[10];
    const float* mean  = (const float*)d_in[11];
    const float* var   = (const float*)d_in[12];
    float* out = (float*)d_out;

    float *p_tpg, *p_phi, *p_f, *p_y;
    __nv_bfloat16 *p_xhT, *p_xlT, *p_thh, *p_thl, *p_phh, *p_phl;
    __nv_bfloat16 *p_gph, *p_gpl, *p_ath, *p_atl, *p_yhT, *p_ylT;
    __nv_bfloat16 *p_whi, *p_wlo, *p_wWhi, *p_wWlo;
    cudaGetSymbolAddress((void**)&p_tpg, g_tpg);
    cudaGetSymbolAddress((void**)&p_phi, g_phi);
    cudaGetSymbolAddress((void**)&p_f, g_f);
    cudaGetSymbolAddress((void**)&p_y, g_y);
    cudaGetSymbolAddress((void**)&p_xhT, g_xhT);
    cudaGetSymbolAddress((void**)&p_xlT, g_xlT);
    cudaGetSymbolAddress((void**)&p_thh, g_thh);
    cudaGetSymbolAddress((void**)&p_thl, g_thl);
    cudaGetSymbolAddress((void**)&p_phh, g_phh);
    cudaGetSymbolAddress((void**)&p_phl, g_phl);
    cudaGetSymbolAddress((void**)&p_gph, g_gph);
    cudaGetSymbolAddress((void**)&p_gpl, g_gpl);
    cudaGetSymbolAddress((void**)&p_ath, g_ath);
    cudaGetSymbolAddress((void**)&p_atl, g_atl);
    cudaGetSymbolAddress((void**)&p_yhT, g_yhT);
    cudaGetSymbolAddress((void**)&p_ylT, g_ylT);
    cudaGetSymbolAddress((void**)&p_whi, g_whi);
    cudaGetSymbolAddress((void**)&p_wlo, g_wlo);
    cudaGetSymbolAddress((void**)&p_wWhi, g_wWhi);
    cudaGetSymbolAddress((void**)&p_wWlo, g_wWlo);

    // 1. weight prep
    {
        long total = (long)CTPG * CC;
        wsplit_stack_kernel<<<(unsigned)((total + 255) / 256), 256>>>(wt, wp, wg, bt, bp, bg);
        wsplitW_kernel<<<(unsigned)(((long)CC * CI + 255) / 256), 256>>>(wW);
        bnprep_kernel<<<(CC + 255) / 256, 256>>>(gamma, beta, mean, var, bW);
    }
    // 2. fused joint + transpose + split
    {
        dim3 grid((NN + 31) / 32, CC / 32, BSZ);
        tsplitX_kernel<<<grid, dim3(32, 8)>>>(x);
    }
    // 3. stacked theta|phi|g conv
    {
        mma128_kernel<1><<<dim3((NN + 127) / 128, CTPG / 128, BSZ), 256>>>(
            p_whi, p_wlo, p_xhT, p_xlT, p_tpg, CC, CTPG, NN,
            0L, (long)NN * CC, NN, (long)CTPG * NN, nullptr);
    }
    // 4. pool
    {
        int total = BSZ * CI * (MM + MMP);
        pool_kernel<<<(total + 255) / 256, 256>>>();
    }
    // 5. theta slice -> theta^T hi/lo
    {
        dim3 grid((NN + 31) / 32, CI / 32, BSZ);
        tsplit_kernel<<<grid, dim3(32, 8)>>>(p_tpg, p_thh, p_thl, CI, NN, (long)CTPG * NN);
    }
    // 6. phi -> phi^T hi/lo
    {
        dim3 grid((MM + 31) / 32, CI / 32, BSZ);
        tsplit_kernel<<<grid, dim3(32, 8)>>>(p_phi, p_phh, p_phl, CI, MM, (long)CI * MM);
    }
    // 7. f = thetaT @ phiT^T
    {
        mma128_kernel<0><<<dim3((MM + 127) / 128, (NN + 127) / 128, BSZ), 256>>>(
            p_thh, p_thl, p_phh, p_phl, p_f, CI, NN, MM,
            (long)NN * CI, (long)MM * CI, MM, (long)NN * MM, nullptr);
    }
    // 8. softmax -> attn hi/lo padded
    {
        int rows = BSZ * NN;
        softmax_kernel<<<(rows * 32 + 255) / 256, 256>>>();
    }
    // 9. y = g @ attn^T
    {
        mma128_kernel<0><<<dim3((NN + 127) / 128, CI / 128, BSZ), 256>>>(
            p_gph, p_gpl, p_ath, p_atl, p_y, MMP, CI, NN,
            (long)CI * MMP, (long)NN * MMP, NN, (long)CI * NN, nullptr);
    }
    // 10. y -> y^T hi/lo
    {
        dim3 grid((NN + 31) / 32, CI / 32, BSZ);
        tsplit_kernel<<<grid, dim3(32, 8)>>>(p_y, p_yhT, p_ylT, CI, NN, (long)CI * NN);
    }
    // 11. W conv + BN + residual (inline joint gather) -> out
    {
        mma128_kernel<2><<<dim3((NN + 127) / 128, CC / 128, BSZ), 256>>>(
            p_wWhi, p_wWlo, p_yhT, p_ylT, out, CI, CC, NN,
            0L, (long)NN * CI, NN, (long)CC * NN, x);
    }
}

// round 7
// speedup vs baseline: 1.4771x; 1.2144x over previous
#include <cuda_runtime.h>
#include <cuda_bf16.h>
#include <cstdint>

// ---------------------------------------------------------------------------
// Problem constants
// ---------------------------------------------------------------------------
#define BSZ  32
#define CC   1536
#define CI   768
#define HH   14
#define WW   14
#define HJ   28
#define WJ   28
#define NN   784
#define MM   196
#define MMP  224          // MM padded to multiple of 32
#define CTPG 2304

// ---------------------------------------------------------------------------
// Scratch (device globals)
// ---------------------------------------------------------------------------
__device__ __align__(16) __nv_bfloat16 g_xhT[(size_t)BSZ * NN * CC];
__device__ __align__(16) __nv_bfloat16 g_xlT[(size_t)BSZ * NN * CC];
__device__ float g_tpg [(size_t)BSZ * CTPG * NN];
__device__ __align__(16) __nv_bfloat16 g_thh[(size_t)BSZ * NN * CI];
__device__ __align__(16) __nv_bfloat16 g_thl[(size_t)BSZ * NN * CI];
__device__ float g_phi [(size_t)BSZ * CI * MM];
__device__ __align__(16) __nv_bfloat16 g_phh[(size_t)BSZ * MM * CI];
__device__ __align__(16) __nv_bfloat16 g_phl[(size_t)BSZ * MM * CI];
__device__ __align__(16) __nv_bfloat16 g_gph[(size_t)BSZ * CI * MMP];
__device__ __align__(16) __nv_bfloat16 g_gpl[(size_t)BSZ * CI * MMP];
__device__ float g_f   [(size_t)BSZ * NN * MM];
__device__ __align__(16) __nv_bfloat16 g_ath[(size_t)BSZ * NN * MMP];
__device__ __align__(16) __nv_bfloat16 g_atl[(size_t)BSZ * NN * MMP];
__device__ float g_y   [(size_t)BSZ * CI * NN];
__device__ __align__(16) __nv_bfloat16 g_yhT[(size_t)BSZ * NN * CI];
__device__ __align__(16) __nv_bfloat16 g_ylT[(size_t)BSZ * NN * CI];
__device__ __align__(16) __nv_bfloat16 g_whi[(size_t)CTPG * CC];
__device__ __align__(16) __nv_bfloat16 g_wlo[(size_t)CTPG * CC];
__device__ __align__(16) __nv_bfloat16 g_wWhi[(size_t)CC * CI];
__device__ __align__(16) __nv_bfloat16 g_wWlo[(size_t)CC * CI];
__device__ float g_bstk[CTPG];
__device__ float g_escale[CC];
__device__ float g_eshift[CC];

// ---------------------------------------------------------------------------
// PTX helpers (base ISA only — harness's ptxas targets plain sm_103)
// ---------------------------------------------------------------------------
__device__ __forceinline__ uint32_t smem_u32(const void* p) {
    uint32_t a;
    asm("{ .reg .u64 t; cvta.to.shared.u64 t, %1; cvt.u32.u64 %0, t; }" : "=r"(a) : "l"(p));
    return a;
}
__device__ __forceinline__ void ldm_x4(uint32_t* r, uint32_t addr) {
    asm volatile("ldmatrix.sync.aligned.m8n8.x4.shared.b16 {%0,%1,%2,%3}, [%4];"
                 : "=r"(r[0]), "=r"(r[1]), "=r"(r[2]), "=r"(r[3]) : "r"(addr));
}
__device__ __forceinline__ void mma16816(float* d, const uint32_t* a, uint32_t b0, uint32_t b1) {
    asm volatile("mma.sync.aligned.m16n8k16.row.col.f32.bf16.bf16.f32 "
                 "{%0,%1,%2,%3}, {%4,%5,%6,%7}, {%8,%9}, {%0,%1,%2,%3};"
                 : "+f"(d[0]), "+f"(d[1]), "+f"(d[2]), "+f"(d[3])
                 : "r"(a[0]), "r"(a[1]), "r"(a[2]), "r"(a[3]), "r"(b0), "r"(b1));
}
__device__ __forceinline__ void cpa16(uint32_t dst, const void* src, int srcsz) {
    asm volatile("cp.async.cg.shared.global [%0], [%1], 16, %2;"
                 :: "r"(dst), "l"(src), "r"(srcsz));
}
#define CPA_COMMIT()  asm volatile("cp.async.commit_group;" ::: "memory")
#define CPA_WAIT(n)   asm volatile("cp.async.wait_group %0;" :: "n"(n) : "memory")

// ---------------------------------------------------------------------------
// fused joint-gather + transpose + bf16 hi/lo split: x -> xjT [b][n][c]
// ---------------------------------------------------------------------------
__global__ void tsplitX_kernel(const float* __restrict__ x) {
    __shared__ float t[32][33];
    int b = blockIdx.z;
    int c0 = blockIdx.y * 32, n0 = blockIdx.x * 32;
    int tx = threadIdx.x, ty = threadIdx.y;
#pragma unroll
    for (int s = 0; s < 32; s += 8) {
        int c = c0 + ty + s, n = n0 + tx;
        float v = 0.f;
        if (n < NN) {
            int hj = n / WJ, wj = n % WJ;
            int vv = ((hj >= HH) ? 2 : 0) + ((wj >= WW) ? 1 : 0);
            int hl = (hj >= HH) ? hj - HH : hj;
            int wl = (wj >= WW) ? wj - WW : wj;
            v = x[(((long)(b * 4 + vv) * CC + c) * HH + hl) * WW + wl];
        }
        t[ty + s][tx] = v;
    }
    __syncthreads();
    long ob = (long)b * NN * CC;
#pragma unroll
    for (int s = 0; s < 32; s += 8) {
        int n = n0 + ty + s, c = c0 + tx;
        if (n < NN) {
            float v = t[tx][ty + s];
            __nv_bfloat16 h = __float2bfloat16(v);
            g_xhT[ob + (long)n * CC + c] = h;
            g_xlT[ob + (long)n * CC + c] = __float2bfloat16(v - __bfloat162float(h));
        }
    }
}

// ---------------------------------------------------------------------------
// generic tiled transpose + bf16 hi/lo split
// ---------------------------------------------------------------------------
__global__ void tsplit_kernel(const float* __restrict__ in,
                              __nv_bfloat16* __restrict__ hi,
                              __nv_bfloat16* __restrict__ lo,
                              int R, int Cn, long inStride) {
    __shared__ float t[32][33];
    int b = blockIdx.z;
    int r0 = blockIdx.y * 32, c0 = blockIdx.x * 32;
    const float* ib = in + (long)b * inStride;
    int tx = threadIdx.x, ty = threadIdx.y;
#pragma unroll
    for (int s = 0; s < 32; s += 8) {
        int r = r0 + ty + s, c = c0 + tx;
        t[ty + s][tx] = (r < R && c < Cn) ? ib[(long)r * Cn + c] : 0.f;
    }
    __syncthreads();
    long ob = (long)b * Cn * R;
#pragma unroll
    for (int s = 0; s < 32; s += 8) {
        int c = c0 + ty + s, r = r0 + tx;
        if (c < Cn && r < R) {
            float v = t[tx][ty + s];
            __nv_bfloat16 h = __float2bfloat16(v);
            hi[ob + (long)c * R + r] = h;
            lo[ob + (long)c * R + r] = __float2bfloat16(v - __bfloat162float(h));
        }
    }
}

// ---------------------------------------------------------------------------
// weight prep
// ---------------------------------------------------------------------------
__global__ void wsplit_stack_kernel(const float* __restrict__ wt, const float* __restrict__ wp,
                                    const float* __restrict__ wg, const float* __restrict__ bt,
                                    const float* __restrict__ bp, const float* __restrict__ bg) {
    long idx = (long)blockIdx.x * blockDim.x + threadIdx.x;
    if (idx < (long)CTPG * CC) {
        int r = (int)(idx / CC), c = (int)(idx % CC);
        const float* src = (r < CI) ? wt : ((r < 2 * CI) ? wp : wg);
        int rr = (r < CI) ? r : ((r < 2 * CI) ? r - CI : r - 2 * CI);
        float v = src[(long)rr * CC + c];
        __nv_bfloat16 h = __float2bfloat16(v);
        g_whi[idx] = h;
        g_wlo[idx] = __float2bfloat16(v - __bfloat162float(h));
    }
    if (idx < CTPG) {
        int r = (int)idx;
        g_bstk[r] = (r < CI) ? bt[r] : ((r < 2 * CI) ? bp[r - CI] : bg[r - 2 * CI]);
    }
}

__global__ void wsplitW_kernel(const float* __restrict__ wW) {
    long idx = (long)blockIdx.x * blockDim.x + threadIdx.x;
    if (idx >= (long)CC * CI) return;
    float v = wW[idx];
    __nv_bfloat16 h = __float2bfloat16(v);
    g_wWhi[idx] = h;
    g_wWlo[idx] = __float2bfloat16(v - __bfloat162float(h));
}

__global__ void bnprep_kernel(const float* __restrict__ gamma, const float* __restrict__ beta,
                              const float* __restrict__ mean, const float* __restrict__ var,
                              const float* __restrict__ bW) {
    int m = blockIdx.x * blockDim.x + threadIdx.x;
    if (m < CC) {
        float s = gamma[m] * rsqrtf(var[m] + 1e-5f);
        g_escale[m] = s;
        g_eshift[m] = beta[m] - mean[m] * s + bW[m] * s;
    }
}

// ---------------------------------------------------------------------------
// 2x2 maxpool: phi -> fp32 [c][196]; g -> bf16 hi/lo [c][224] padded
// ---------------------------------------------------------------------------
__global__ void pool_kernel() {
    int idx = blockIdx.x * blockDim.x + threadIdx.x;
    const int totPhi = BSZ * CI * MM;
    const int totG = BSZ * CI * MMP;
    if (idx < totPhi) {
        int m = idx % MM;
        int c = (idx / MM) % CI;
        int b = idx / (MM * CI);
        int hm = m / 14, wm = m % 14;
        const float* src = g_tpg + ((long)b * CTPG + CI + c) * NN;
        int base = (2 * hm) * WJ + 2 * wm;
        g_phi[idx] = fmaxf(fmaxf(src[base], src[base + 1]),
                           fmaxf(src[base + WJ], src[base + WJ + 1]));
    } else if (idx < totPhi + totG) {
        int r = idx - totPhi;
        int j = r % MMP;
        int c = (r / MMP) % CI;
        int b = r / (MMP * CI);
        float v = 0.f;
        if (j < MM) {
            int hm = j / 14, wm = j % 14;
            const float* src = g_tpg + ((long)b * CTPG + 2 * CI + c) * NN;
            int base = (2 * hm) * WJ + 2 * wm;
            v = fmaxf(fmaxf(src[base], src[base + 1]),
                      fmaxf(src[base + WJ], src[base + WJ + 1]));
        }
        __nv_bfloat16 h = __float2bfloat16(v);
        g_gph[r] = h;
        g_gpl[r] = (j < MM) ? __float2bfloat16(v - __bfloat162float(h)) : __nv_bfloat16(0.f);
    }
}

// ---------------------------------------------------------------------------
// row softmax over MM=196 -> attn hi/lo bf16 padded [n][224]
// ---------------------------------------------------------------------------
__global__ void softmax_kernel() {
    int warp = (blockIdx.x * blockDim.x + threadIdx.x) >> 5;
    int lane = threadIdx.x & 31;
    if (warp >= BSZ * NN) return;
    const float* row = g_f + (long)warp * MM;
    __nv_bfloat16* oh = g_ath + (long)warp * MMP;
    __nv_bfloat16* ol = g_atl + (long)warp * MMP;
    float vals[7];
    float mx = -1e30f;
#pragma unroll
    for (int s = 0; s < 7; s++) {
        int i = lane + s * 32;
        vals[s] = (i < MM) ? row[i] : -1e30f;
        mx = fmaxf(mx, vals[s]);
    }
#pragma unroll
    for (int o = 16; o; o >>= 1) mx = fmaxf(mx, __shfl_xor_sync(0xffffffffu, mx, o));
    float sum = 0.f;
#pragma unroll
    for (int s = 0; s < 7; s++) {
        int i = lane + s * 32;
        vals[s] = (i < MM) ? __expf(vals[s] - mx) : 0.f;
        sum += vals[s];
    }
#pragma unroll
    for (int o = 16; o; o >>= 1) sum += __shfl_xor_sync(0xffffffffu, sum, o);
    float inv = 1.f / sum;
#pragma unroll
    for (int s = 0; s < 7; s++) {
        int i = lane + s * 32;   // 0..223 == MMP
        float v = vals[s] * inv;
        __nv_bfloat16 h = __float2bfloat16(v);
        oh[i] = h;
        ol[i] = __float2bfloat16(v - __bfloat162float(h));
    }
}

// ---------------------------------------------------------------------------
// fused-pass bf16-split tensor GEMM (mma.sync m16n8k16).
//   128x128 CTA tile, 256 threads, 2 CTAs/SM, 2-stage cp.async pipeline.
//   Per K-chunk: load Ahi/Alo/Bhi/Blo once; mma hi*hi + hi*lo + lo*hi into the
//   same fp32 accumulators (error ~1e-5, vs ~1e-3 for plain bf16).
//   EPI 0: plain   EPI 1: +g_bstk[m]   EPI 2: BN-fold + residual joint(x)
// ---------------------------------------------------------------------------
#define GTILE (128 * 40)

template <int EPI>
__global__ void __launch_bounds__(256, 2)
mma128_kernel(const __nv_bfloat16* __restrict__ Ahi, const __nv_bfloat16* __restrict__ Alo,
              const __nv_bfloat16* __restrict__ Bhi, const __nv_bfloat16* __restrict__ Blo,
              float* __restrict__ Cp, int K, int MV, int NB,
              long strideA, long strideB, int ldC, long sC,
              const float* __restrict__ xres) {
    extern __shared__ __align__(16) __nv_bfloat16 smem[];
    constexpr int ST = GTILE * 4;   // per-stage: [Ahi | Bhi | Alo | Blo]

    const int tid = threadIdx.x;
    const int lane = tid & 31;
    const int wid = tid >> 5;
    const int wm = wid & 1;          // 2 M-warps -> 64 rows
    const int wn = wid >> 1;         // 4 N-warps -> 32 cols
    const int m0 = blockIdx.y * 128;
    const int n0 = blockIdx.x * 128;
    const int b  = blockIdx.z;

    const int NK = K / 32;
    const __nv_bfloat16* A0 = Ahi + (long)b * strideA + (long)m0 * K;
    const __nv_bfloat16* A1 = Alo + (long)b * strideA + (long)m0 * K;
    const __nv_bfloat16* B0 = Bhi + (long)b * strideB;
    const __nv_bfloat16* B1 = Blo + (long)b * strideB;

    float acc[4][4][4];
#pragma unroll
    for (int i = 0; i < 4; i++)
#pragma unroll
        for (int j = 0; j < 4; j++)
#pragma unroll
            for (int r = 0; r < 4; r++) acc[i][j][r] = 0.f;

    auto loadChunk = [&](int g, int buf) {
        long kc = (long)g * 32;
        __nv_bfloat16* st = smem + buf * ST;
#pragma unroll
        for (int i = 0; i < 2; i++) {
            int idx = tid + i * 256;
            int row = idx >> 2, seg = idx & 3;
            int off = row * 40 + seg * 8;
            long ga = (long)row * K + kc + seg * 8;
            int okA = (m0 + row) < MV;
            int okB = (n0 + row) < NB;
            long gb = (long)(okB ? (n0 + row) : 0) * K + kc + seg * 8;
            cpa16(smem_u32(st + off), A0 + ga, okA ? 16 : 0);
            cpa16(smem_u32(st + GTILE + off), B0 + gb, okB ? 16 : 0);
            cpa16(smem_u32(st + 2 * GTILE + off), A1 + ga, okA ? 16 : 0);
            cpa16(smem_u32(st + 3 * GTILE + off), B1 + gb, okB ? 16 : 0);
        }
    };

    loadChunk(0, 0);
    CPA_COMMIT();

    for (int g = 0; g < NK; g++) {
        int buf = g & 1;
        if (g + 1 < NK) {
            loadChunk(g + 1, buf ^ 1);
            CPA_COMMIT();
            CPA_WAIT(1);
        } else {
            CPA_WAIT(0);
        }
        __syncthreads();
        const __nv_bfloat16* st = smem + buf * ST;

#pragma unroll
        for (int ks = 0; ks < 2; ks++) {
            const int aRow = wm * 64 + ((lane >> 3) & 1) * 8 + (lane & 7);
            const int aCol = ks * 16 + (lane >> 4) * 8;
            const int bRow = wn * 32 + (lane >> 4) * 8 + (lane & 7);
            const int bCol = ks * 16 + ((lane >> 3) & 1) * 8;

            uint32_t bh[2][4];
#pragma unroll
            for (int ni = 0; ni < 2; ni++)
                ldm_x4(bh[ni], smem_u32(st + GTILE + (bRow + ni * 16) * 40 + bCol));

            uint32_t a[4][4];
#pragma unroll
            for (int mi = 0; mi < 4; mi++)
                ldm_x4(a[mi], smem_u32(st + (aRow + mi * 16) * 40 + aCol));

            // hi * hi
#pragma unroll
            for (int mi = 0; mi < 4; mi++)
#pragma unroll
                for (int nj = 0; nj < 4; nj++)
                    mma16816(acc[mi][nj], a[mi],
                             bh[nj >> 1][(nj & 1) * 2], bh[nj >> 1][(nj & 1) * 2 + 1]);

            // hi * lo
            uint32_t bl[2][4];
#pragma unroll
            for (int ni = 0; ni < 2; ni++)
                ldm_x4(bl[ni], smem_u32(st + 3 * GTILE + (bRow + ni * 16) * 40 + bCol));
#pragma unroll
            for (int mi = 0; mi < 4; mi++)
#pragma unroll
                for (int nj = 0; nj < 4; nj++)
                    mma16816(acc[mi][nj], a[mi],
                             bl[nj >> 1][(nj & 1) * 2], bl[nj >> 1][(nj & 1) * 2 + 1]);

            // lo * hi (reuse a regs)
#pragma unroll
            for (int mi = 0; mi < 4; mi++)
                ldm_x4(a[mi], smem_u32(st + 2 * GTILE + (aRow + mi * 16) * 40 + aCol));
#pragma unroll
            for (int mi = 0; mi < 4; mi++)
#pragma unroll
                for (int nj = 0; nj < 4; nj++)
                    mma16816(acc[mi][nj], a[mi],
                             bh[nj >> 1][(nj & 1) * 2], bh[nj >> 1][(nj & 1) * 2 + 1]);
        }
        __syncthreads();
    }

    // epilogue
    const int mbase = m0 + wm * 64;
    const int nbase = n0 + wn * 32;
    float* Cb = Cp + (long)b * sC;
#pragma unroll
    for (int mi = 0; mi < 4; mi++) {
        int mr0 = mbase + mi * 16 + (lane >> 2);
        int mr1 = mr0 + 8;
        bool ok0 = mr0 < MV, ok1 = mr1 < MV;
        float es0 = 1.f, eh0 = 0.f, es1 = 1.f, eh1 = 0.f;
        if (EPI == 1) { if (ok0) eh0 = g_bstk[mr0]; if (ok1) eh1 = g_bstk[mr1]; }
        if (EPI == 2) {
            if (ok0) { es0 = g_escale[mr0]; eh0 = g_eshift[mr0]; }
            if (ok1) { es1 = g_escale[mr1]; eh1 = g_eshift[mr1]; }
        }
#pragma unroll
        for (int nj = 0; nj < 4; nj++) {
            int n = nbase + nj * 8 + (lane & 3) * 2;
            if (n >= NB) continue;
            float2 v0 = make_float2(acc[mi][nj][0], acc[mi][nj][1]);
            float2 v1 = make_float2(acc[mi][nj][2], acc[mi][nj][3]);
            if (EPI == 2) {
                int hj = n / WJ, wj0 = n - hj * WJ;
#pragma unroll
                for (int e = 0; e < 2; e++) {
                    int wj = wj0 + e;
                    int vv = ((hj >= HH) ? 2 : 0) + ((wj >= WW) ? 1 : 0);
                    int hl = (hj >= HH) ? hj - HH : hj;
                    int wl = (wj >= WW) ? wj - WW : wj;
                    long base = (((long)(b * 4 + vv) * CC) * HH + hl) * WW + wl;
                    float r0 = ok0 ? xres[base + (long)mr0 * HH * WW] : 0.f;
                    float r1 = ok1 ? xres[base + (long)mr1 * HH * WW] : 0.f;
                    if (e == 0) { v0.x = v0.x * es0 + eh0 + r0; v1.x = v1.x * es1 + eh1 + r1; }
                    else        { v0.y = v0.y * es0 + eh0 + r0; v1.y = v1.y * es1 + eh1 + r1; }
                }
            } else {
                v0.x = v0.x * es0 + eh0; v0.y = v0.y * es0 + eh0;
                v1.x = v1.x * es1 + eh1; v1.y = v1.y * es1 + eh1;
            }
            if (ok0) *(float2*)(Cb + (long)mr0 * ldC + n) = v0;
            if (ok1) *(float2*)(Cb + (long)mr1 * ldC + n) = v1;
        }
    }
}

#define SMEM3 (2 * 4 * GTILE * 2)   // 81920 B (2 stages x 4 tiles x bf16)

// ---------------------------------------------------------------------------
// Launch
// ---------------------------------------------------------------------------
extern "C" void kernel_launch(void* const* d_in, const int* in_sizes, int n_in,
                              void* d_out, int out_size) {
    const float* x     = (const float*)d_in[0];
    const float* wt    = (const float*)d_in[1];
    const float* bt    = (const float*)d_in[2];
    const float* wp    = (const float*)d_in[3];
    const float* bp    = (const float*)d_in[4];
    const float* wg    = (const float*)d_in[5];
    const float* bg    = (const float*)d_in[6];
    const float* wW    = (const float*)d_in[7];
    const float* bW    = (const float*)d_in[8];
    const float* gamma = (const float*)d_in[9];
    const float* beta  = (const float*)d_in[10];
    const float* mean  = (const float*)d_in[11];
    const float* var   = (const float*)d_in[12];
    float* out = (float*)d_out;

    float *p_tpg, *p_phi, *p_f, *p_y;
    __nv_bfloat16 *p_xhT, *p_xlT, *p_thh, *p_thl, *p_phh, *p_phl;
    __nv_bfloat16 *p_gph, *p_gpl, *p_ath, *p_atl, *p_yhT, *p_ylT;
    __nv_bfloat16 *p_whi, *p_wlo, *p_wWhi, *p_wWlo;
    cudaGetSymbolAddress((void**)&p_tpg, g_tpg);
    cudaGetSymbolAddress((void**)&p_phi, g_phi);
    cudaGetSymbolAddress((void**)&p_f, g_f);
    cudaGetSymbolAddress((void**)&p_y, g_y);
    cudaGetSymbolAddress((void**)&p_xhT, g_xhT);
    cudaGetSymbolAddress((void**)&p_xlT, g_xlT);
    cudaGetSymbolAddress((void**)&p_thh, g_thh);
    cudaGetSymbolAddress((void**)&p_thl, g_thl);
    cudaGetSymbolAddress((void**)&p_phh, g_phh);
    cudaGetSymbolAddress((void**)&p_phl, g_phl);
    cudaGetSymbolAddress((void**)&p_gph, g_gph);
    cudaGetSymbolAddress((void**)&p_gpl, g_gpl);
    cudaGetSymbolAddress((void**)&p_ath, g_ath);
    cudaGetSymbolAddress((void**)&p_atl, g_atl);
    cudaGetSymbolAddress((void**)&p_yhT, g_yhT);
    cudaGetSymbolAddress((void**)&p_ylT, g_ylT);
    cudaGetSymbolAddress((void**)&p_whi, g_whi);
    cudaGetSymbolAddress((void**)&p_wlo, g_wlo);
    cudaGetSymbolAddress((void**)&p_wWhi, g_wWhi);
    cudaGetSymbolAddress((void**)&p_wWlo, g_wWlo);

    cudaFuncSetAttribute((const void*)mma128_kernel<0>,
                         cudaFuncAttributeMaxDynamicSharedMemorySize, SMEM3);
    cudaFuncSetAttribute((const void*)mma128_kernel<1>,
                         cudaFuncAttributeMaxDynamicSharedMemorySize, SMEM3);
    cudaFuncSetAttribute((const void*)mma128_kernel<2>,
                         cudaFuncAttributeMaxDynamicSharedMemorySize, SMEM3);

    // #1 weight stack+split (needed by GEMM1)
    {
        long total = (long)CTPG * CC;
        wsplit_stack_kernel<<<(unsigned)((total + 255) / 256), 256>>>(wt, wp, wg, bt, bp, bg);
    }
    // #2 fused joint + transpose + split
    {
        dim3 grid((NN + 31) / 32, CC / 32, BSZ);
        tsplitX_kernel<<<grid, dim3(32, 8)>>>(x);
    }
    // #3 BN prep (placed here so GEMM1 is launch #4 for ncu)
    bnprep_kernel<<<(CC + 255) / 256, 256>>>(gamma, beta, mean, var, bW);
    // #4 stacked theta|phi|g conv  (ncu captures this launch)
    {
        mma128_kernel<1><<<dim3((NN + 127) / 128, CTPG / 128, BSZ), 256, SMEM3>>>(
            p_whi, p_wlo, p_xhT, p_xlT, p_tpg, CC, CTPG, NN,
            0L, (long)NN * CC, NN, (long)CTPG * NN, nullptr);
    }
    // #5 W-conv weight split
    wsplitW_kernel<<<(unsigned)(((long)CC * CI + 255) / 256), 256>>>(wW);
    // #6 pool
    {
        int total = BSZ * CI * (MM + MMP);
        pool_kernel<<<(total + 255) / 256, 256>>>();
    }
    // #7 theta slice -> theta^T hi/lo
    {
        dim3 grid((NN + 31) / 32, CI / 32, BSZ);
        tsplit_kernel<<<grid, dim3(32, 8)>>>(p_tpg, p_thh, p_thl, CI, NN, (long)CTPG * NN);
    }
    // #8 phi -> phi^T hi/lo
    {
        dim3 grid((MM + 31) / 32, CI / 32, BSZ);
        tsplit_kernel<<<grid, dim3(32, 8)>>>(p_phi, p_phh, p_phl, CI, MM, (long)CI * MM);
    }
    // #9 f = thetaT @ phiT^T
    {
        mma128_kernel<0><<<dim3((MM + 127) / 128, (NN + 127) / 128, BSZ), 256, SMEM3>>>(
            p_thh, p_thl, p_phh, p_phl, p_f, CI, NN, MM,
            (long)NN * CI, (long)MM * CI, MM, (long)NN * MM, nullptr);
    }
    // #10 softmax -> attn hi/lo padded
    {
        int rows = BSZ * NN;
        softmax_kernel<<<(rows * 32 + 255) / 256, 256>>>();
    }
    // #11 y = g @ attn^T
    {
        mma128_kernel<0><<<dim3((NN + 127) / 128, CI / 128, BSZ), 256, SMEM3>>>(
            p_gph, p_gpl, p_ath, p_atl, p_y, MMP, CI, NN,
            (long)CI * MMP, (long)NN * MMP, NN, (long)CI * NN, nullptr);
    }
    // #12 y -> y^T hi/lo
    {
        dim3 grid((NN + 31) / 32, CI / 32, BSZ);
        tsplit_kernel<<<grid, dim3(32, 8)>>>(p_y, p_yhT, p_ylT, CI, NN, (long)CI * NN);
    }
    // #13 W conv (3-pass split) + BN + residual -> out
    {
        mma128_kernel<2><<<dim3((NN + 127) / 128, CC / 128, BSZ), 256, SMEM3>>>(
            p_wWhi, p_wWlo, p_yhT, p_ylT, out, CI, CC, NN,
            0L, (long)NN * CI, NN, (long)CC * NN, x);
    }
}

// round 8
// speedup vs baseline: 1.7048x; 1.1541x over previous
#include <cuda_runtime.h>
#include <cuda_bf16.h>
#include <cstdint>

// ---------------------------------------------------------------------------
// Problem constants
// ---------------------------------------------------------------------------
#define BSZ  32
#define CC   1536
#define CI   768
#define HH   14
#define WW   14
#define HJ   28
#define WJ   28
#define NN   784
#define MM   196
#define MMP  224          // MM padded to multiple of 32
#define CTPG 2304

// ---------------------------------------------------------------------------
// Scratch (device globals)
// ---------------------------------------------------------------------------
__device__ __align__(16) __nv_bfloat16 g_xhT[(size_t)BSZ * NN * CC];
__device__ __align__(16) __nv_bfloat16 g_xlT[(size_t)BSZ * NN * CC];
__device__ float g_tpg [(size_t)BSZ * CTPG * NN];
__device__ __align__(16) __nv_bfloat16 g_thh[(size_t)BSZ * NN * CI];
__device__ __align__(16) __nv_bfloat16 g_thl[(size_t)BSZ * NN * CI];
__device__ float g_phi [(size_t)BSZ * CI * MM];
__device__ __align__(16) __nv_bfloat16 g_phh[(size_t)BSZ * MM * CI];
__device__ __align__(16) __nv_bfloat16 g_phl[(size_t)BSZ * MM * CI];
__device__ __align__(16) __nv_bfloat16 g_gph[(size_t)BSZ * CI * MMP];
__device__ __align__(16) __nv_bfloat16 g_gpl[(size_t)BSZ * CI * MMP];
__device__ float g_f   [(size_t)BSZ * NN * MM];
__device__ __align__(16) __nv_bfloat16 g_ath[(size_t)BSZ * NN * MMP];
__device__ __align__(16) __nv_bfloat16 g_atl[(size_t)BSZ * NN * MMP];
__device__ float g_y   [(size_t)BSZ * CI * NN];
__device__ __align__(16) __nv_bfloat16 g_yhT[(size_t)BSZ * NN * CI];
__device__ __align__(16) __nv_bfloat16 g_ylT[(size_t)BSZ * NN * CI];
__device__ __align__(16) __nv_bfloat16 g_whi[(size_t)CTPG * CC];
__device__ __align__(16) __nv_bfloat16 g_wlo[(size_t)CTPG * CC];
__device__ __align__(16) __nv_bfloat16 g_wWhi[(size_t)CC * CI];
__device__ __align__(16) __nv_bfloat16 g_wWlo[(size_t)CC * CI];
__device__ float g_bstk[CTPG];
__device__ float g_escale[CC];
__device__ float g_eshift[CC];

// ---------------------------------------------------------------------------
// PTX helpers (base ISA only — harness's ptxas targets plain sm_103)
// ---------------------------------------------------------------------------
__device__ __forceinline__ uint32_t smem_u32(const void* p) {
    uint32_t a;
    asm("{ .reg .u64 t; cvta.to.shared.u64 t, %1; cvt.u32.u64 %0, t; }" : "=r"(a) : "l"(p));
    return a;
}
__device__ __forceinline__ void ldm_x4(uint32_t* r, uint32_t addr) {
    asm volatile("ldmatrix.sync.aligned.m8n8.x4.shared.b16 {%0,%1,%2,%3}, [%4];"
                 : "=r"(r[0]), "=r"(r[1]), "=r"(r[2]), "=r"(r[3]) : "r"(addr));
}
__device__ __forceinline__ void mma16816(float* d, const uint32_t* a, uint32_t b0, uint32_t b1) {
    asm volatile("mma.sync.aligned.m16n8k16.row.col.f32.bf16.bf16.f32 "
                 "{%0,%1,%2,%3}, {%4,%5,%6,%7}, {%8,%9}, {%0,%1,%2,%3};"
                 : "+f"(d[0]), "+f"(d[1]), "+f"(d[2]), "+f"(d[3])
                 : "r"(a[0]), "r"(a[1]), "r"(a[2]), "r"(a[3]), "r"(b0), "r"(b1));
}
__device__ __forceinline__ void cpa16(uint32_t dst, const void* src, int srcsz) {
    asm volatile("cp.async.cg.shared.global [%0], [%1], 16, %2;"
                 :: "r"(dst), "l"(src), "r"(srcsz));
}
#define CPA_COMMIT()  asm volatile("cp.async.commit_group;" ::: "memory")
#define CPA_WAIT(n)   asm volatile("cp.async.wait_group %0;" :: "n"(n) : "memory")

// ---------------------------------------------------------------------------
// fused joint-gather + transpose + bf16 hi/lo split: x -> xjT [b][n][c]
// ---------------------------------------------------------------------------
__global__ void tsplitX_kernel(const float* __restrict__ x) {
    __shared__ float t[32][33];
    int b = blockIdx.z;
    int c0 = blockIdx.y * 32, n0 = blockIdx.x * 32;
    int tx = threadIdx.x, ty = threadIdx.y;
#pragma unroll
    for (int s = 0; s < 32; s += 8) {
        int c = c0 + ty + s, n = n0 + tx;
        float v = 0.f;
        if (n < NN) {
            int hj = n / WJ, wj = n % WJ;
            int vv = ((hj >= HH) ? 2 : 0) + ((wj >= WW) ? 1 : 0);
            int hl = (hj >= HH) ? hj - HH : hj;
            int wl = (wj >= WW) ? wj - WW : wj;
            v = x[(((long)(b * 4 + vv) * CC + c) * HH + hl) * WW + wl];
        }
        t[ty + s][tx] = v;
    }
    __syncthreads();
    long ob = (long)b * NN * CC;
#pragma unroll
    for (int s = 0; s < 32; s += 8) {
        int n = n0 + ty + s, c = c0 + tx;
        if (n < NN) {
            float v = t[tx][ty + s];
            __nv_bfloat16 h = __float2bfloat16(v);
            g_xhT[ob + (long)n * CC + c] = h;
            g_xlT[ob + (long)n * CC + c] = __float2bfloat16(v - __bfloat162float(h));
        }
    }
}

// ---------------------------------------------------------------------------
// generic tiled transpose + bf16 hi/lo split
// ---------------------------------------------------------------------------
__global__ void tsplit_kernel(const float* __restrict__ in,
                              __nv_bfloat16* __restrict__ hi,
                              __nv_bfloat16* __restrict__ lo,
                              int R, int Cn, long inStride) {
    __shared__ float t[32][33];
    int b = blockIdx.z;
    int r0 = blockIdx.y * 32, c0 = blockIdx.x * 32;
    const float* ib = in + (long)b * inStride;
    int tx = threadIdx.x, ty = threadIdx.y;
#pragma unroll
    for (int s = 0; s < 32; s += 8) {
        int r = r0 + ty + s, c = c0 + tx;
        t[ty + s][tx] = (r < R && c < Cn) ? ib[(long)r * Cn + c] : 0.f;
    }
    __syncthreads();
    long ob = (long)b * Cn * R;
#pragma unroll
    for (int s = 0; s < 32; s += 8) {
        int c = c0 + ty + s, r = r0 + tx;
        if (c < Cn && r < R) {
            float v = t[tx][ty + s];
            __nv_bfloat16 h = __float2bfloat16(v);
            hi[ob + (long)c * R + r] = h;
            lo[ob + (long)c * R + r] = __float2bfloat16(v - __bfloat162float(h));
        }
    }
}

// ---------------------------------------------------------------------------
// weight prep
// ---------------------------------------------------------------------------
__global__ void wsplit_stack_kernel(const float* __restrict__ wt, const float* __restrict__ wp,
                                    const float* __restrict__ wg, const float* __restrict__ bt,
                                    const float* __restrict__ bp, const float* __restrict__ bg) {
    long idx = (long)blockIdx.x * blockDim.x + threadIdx.x;
    if (idx < (long)CTPG * CC) {
        int r = (int)(idx / CC), c = (int)(idx % CC);
        const float* src = (r < CI) ? wt : ((r < 2 * CI) ? wp : wg);
        int rr = (r < CI) ? r : ((r < 2 * CI) ? r - CI : r - 2 * CI);
        float v = src[(long)rr * CC + c];
        __nv_bfloat16 h = __float2bfloat16(v);
        g_whi[idx] = h;
        g_wlo[idx] = __float2bfloat16(v - __bfloat162float(h));
    }
    if (idx < CTPG) {
        int r = (int)idx;
        g_bstk[r] = (r < CI) ? bt[r] : ((r < 2 * CI) ? bp[r - CI] : bg[r - 2 * CI]);
    }
}

__global__ void wsplitW_kernel(const float* __restrict__ wW) {
    long idx = (long)blockIdx.x * blockDim.x + threadIdx.x;
    if (idx >= (long)CC * CI) return;
    float v = wW[idx];
    __nv_bfloat16 h = __float2bfloat16(v);
    g_wWhi[idx] = h;
    g_wWlo[idx] = __float2bfloat16(v - __bfloat162float(h));
}

__global__ void bnprep_kernel(const float* __restrict__ gamma, const float* __restrict__ beta,
                              const float* __restrict__ mean, const float* __restrict__ var,
                              const float* __restrict__ bW) {
    int m = blockIdx.x * blockDim.x + threadIdx.x;
    if (m < CC) {
        float s = gamma[m] * rsqrtf(var[m] + 1e-5f);
        g_escale[m] = s;
        g_eshift[m] = beta[m] - mean[m] * s + bW[m] * s;
    }
}

// ---------------------------------------------------------------------------
// 2x2 maxpool: phi -> fp32 [c][196]; g -> bf16 hi/lo [c][224] padded
// ---------------------------------------------------------------------------
__global__ void pool_kernel() {
    int idx = blockIdx.x * blockDim.x + threadIdx.x;
    const int totPhi = BSZ * CI * MM;
    const int totG = BSZ * CI * MMP;
    if (idx < totPhi) {
        int m = idx % MM;
        int c = (idx / MM) % CI;
        int b = idx / (MM * CI);
        int hm = m / 14, wm = m % 14;
        const float* src = g_tpg + ((long)b * CTPG + CI + c) * NN;
        int base = (2 * hm) * WJ + 2 * wm;
        g_phi[idx] = fmaxf(fmaxf(src[base], src[base + 1]),
                           fmaxf(src[base + WJ], src[base + WJ + 1]));
    } else if (idx < totPhi + totG) {
        int r = idx - totPhi;
        int j = r % MMP;
        int c = (r / MMP) % CI;
        int b = r / (MMP * CI);
        float v = 0.f;
        if (j < MM) {
            int hm = j / 14, wm = j % 14;
            const float* src = g_tpg + ((long)b * CTPG + 2 * CI + c) * NN;
            int base = (2 * hm) * WJ + 2 * wm;
            v = fmaxf(fmaxf(src[base], src[base + 1]),
                      fmaxf(src[base + WJ], src[base + WJ + 1]));
        }
        __nv_bfloat16 h = __float2bfloat16(v);
        g_gph[r] = h;
        g_gpl[r] = (j < MM) ? __float2bfloat16(v - __bfloat162float(h)) : __nv_bfloat16(0.f);
    }
}

// ---------------------------------------------------------------------------
// row softmax over MM=196 -> attn hi/lo bf16 padded [n][224]
// ---------------------------------------------------------------------------
__global__ void softmax_kernel() {
    int warp = (blockIdx.x * blockDim.x + threadIdx.x) >> 5;
    int lane = threadIdx.x & 31;
    if (warp >= BSZ * NN) return;
    const float* row = g_f + (long)warp * MM;
    __nv_bfloat16* oh = g_ath + (long)warp * MMP;
    __nv_bfloat16* ol = g_atl + (long)warp * MMP;
    float vals[7];
    float mx = -1e30f;
#pragma unroll
    for (int s = 0; s < 7; s++) {
        int i = lane + s * 32;
        vals[s] = (i < MM) ? row[i] : -1e30f;
        mx = fmaxf(mx, vals[s]);
    }
#pragma unroll
    for (int o = 16; o; o >>= 1) mx = fmaxf(mx, __shfl_xor_sync(0xffffffffu, mx, o));
    float sum = 0.f;
#pragma unroll
    for (int s = 0; s < 7; s++) {
        int i = lane + s * 32;
        vals[s] = (i < MM) ? __expf(vals[s] - mx) : 0.f;
        sum += vals[s];
    }
#pragma unroll
    for (int o = 16; o; o >>= 1) sum += __shfl_xor_sync(0xffffffffu, sum, o);
    float inv = 1.f / sum;
#pragma unroll
    for (int s = 0; s < 7; s++) {
        int i = lane + s * 32;   // 0..223 == MMP
        float v = vals[s] * inv;
        __nv_bfloat16 h = __float2bfloat16(v);
        oh[i] = h;
        ol[i] = __float2bfloat16(v - __bfloat162float(h));
    }
}

// ---------------------------------------------------------------------------
// fused-pass bf16-split tensor GEMM (mma.sync m16n8k16).
//   128x128 CTA tile, 256 threads, 2 CTAs/SM.
//   3-stage cp.async pipeline with swizzled 64B-row smem tiles and a single
//   __syncthreads() per K-chunk.
//   Per K-chunk: load Ahi/Alo/Bhi/Blo once; mma hi*hi + hi*lo + lo*hi.
//   EPI 0: plain   EPI 1: +g_bstk[m]   EPI 2: BN-fold + residual joint(x)
// ---------------------------------------------------------------------------
#define GTILE (128 * 32)            // bf16 elems per tile (128 rows x 64B)
#define ST    (4 * GTILE)           // per-stage: [Ahi | Bhi | Alo | Blo]
#define SMEM3 (3 * ST * 2)          // 98304 B

// swizzled element offset within a tile: row-major 64B rows, 16B segs XORed
__device__ __forceinline__ int swz(int row, int seg) {
    return row * 32 + ((seg ^ ((row >> 1) & 3)) << 3);
}

template <int EPI>
__global__ void __launch_bounds__(256, 2)
mma128_kernel(const __nv_bfloat16* __restrict__ Ahi, const __nv_bfloat16* __restrict__ Alo,
              const __nv_bfloat16* __restrict__ Bhi, const __nv_bfloat16* __restrict__ Blo,
              float* __restrict__ Cp, int K, int MV, int NB,
              long strideA, long strideB, int ldC, long sC,
              const float* __restrict__ xres) {
    extern __shared__ __align__(16) __nv_bfloat16 smem[];

    const int tid = threadIdx.x;
    const int lane = tid & 31;
    const int wid = tid >> 5;
    const int wm = wid & 1;          // 2 M-warps -> 64 rows
    const int wn = wid >> 1;         // 4 N-warps -> 32 cols
    const int m0 = blockIdx.y * 128;
    const int n0 = blockIdx.x * 128;
    const int b  = blockIdx.z;

    const int NK = K / 32;           // >= 7 for all call sites
    const __nv_bfloat16* A0 = Ahi + (long)b * strideA + (long)m0 * K;
    const __nv_bfloat16* A1 = Alo + (long)b * strideA + (long)m0 * K;
    const __nv_bfloat16* B0 = Bhi + (long)b * strideB;
    const __nv_bfloat16* B1 = Blo + (long)b * strideB;

    float acc[4][4][4];
#pragma unroll
    for (int i = 0; i < 4; i++)
#pragma unroll
        for (int j = 0; j < 4; j++)
#pragma unroll
            for (int r = 0; r < 4; r++) acc[i][j][r] = 0.f;

    auto loadChunk = [&](int g, int stage) {
        long kc = (long)g * 32;
        __nv_bfloat16* st = smem + stage * ST;
#pragma unroll
        for (int i = 0; i < 2; i++) {
            int idx = tid + i * 256;
            int row = idx >> 2, seg = idx & 3;
            int off = swz(row, seg);
            long ga = (long)row * K + kc + seg * 8;
            int okA = (m0 + row) < MV;
            int okB = (n0 + row) < NB;
            long gb = (long)(okB ? (n0 + row) : 0) * K + kc + seg * 8;
            cpa16(smem_u32(st + off), A0 + ga, okA ? 16 : 0);
            cpa16(smem_u32(st + GTILE + off), B0 + gb, okB ? 16 : 0);
            cpa16(smem_u32(st + 2 * GTILE + off), A1 + ga, okA ? 16 : 0);
            cpa16(smem_u32(st + 3 * GTILE + off), B1 + gb, okB ? 16 : 0);
        }
    };

    loadChunk(0, 0); CPA_COMMIT();
    loadChunk(1, 1); CPA_COMMIT();

    int cs = 0;   // compute stage
    int ls = 2;   // next load stage
    for (int g = 0; g < NK; g++) {
        if (g + 1 < NK) { CPA_WAIT(1); } else { CPA_WAIT(0); }
        __syncthreads();
        if (g + 2 < NK) {
            loadChunk(g + 2, ls);
            CPA_COMMIT();
            ls = (ls == 2) ? 0 : ls + 1;
        }
        const __nv_bfloat16* st = smem + cs * ST;
        cs = (cs == 2) ? 0 : cs + 1;

#pragma unroll
        for (int ks = 0; ks < 2; ks++) {
            const int aRow = wm * 64 + ((lane >> 3) & 1) * 8 + (lane & 7);
            const int aSeg = ks * 2 + (lane >> 4);
            const int bRow = wn * 32 + (lane >> 4) * 8 + (lane & 7);
            const int bSeg = ks * 2 + ((lane >> 3) & 1);

            uint32_t bh[2][4];
#pragma unroll
            for (int ni = 0; ni < 2; ni++)
                ldm_x4(bh[ni], smem_u32(st + GTILE + swz(bRow + ni * 16, bSeg)));

            uint32_t a[4][4];
#pragma unroll
            for (int mi = 0; mi < 4; mi++)
                ldm_x4(a[mi], smem_u32(st + swz(aRow + mi * 16, aSeg)));

            // hi * hi
#pragma unroll
            for (int mi = 0; mi < 4; mi++)
#pragma unroll
                for (int nj = 0; nj < 4; nj++)
                    mma16816(acc[mi][nj], a[mi],
                             bh[nj >> 1][(nj & 1) * 2], bh[nj >> 1][(nj & 1) * 2 + 1]);

            // hi * lo
            uint32_t bl[2][4];
#pragma unroll
            for (int ni = 0; ni < 2; ni++)
                ldm_x4(bl[ni], smem_u32(st + 3 * GTILE + swz(bRow + ni * 16, bSeg)));
#pragma unroll
            for (int mi = 0; mi < 4; mi++)
#pragma unroll
                for (int nj = 0; nj < 4; nj++)
                    mma16816(acc[mi][nj], a[mi],
                             bl[nj >> 1][(nj & 1) * 2], bl[nj >> 1][(nj & 1) * 2 + 1]);

            // lo * hi (reuse a regs)
#pragma unroll
            for (int mi = 0; mi < 4; mi++)
                ldm_x4(a[mi], smem_u32(st + 2 * GTILE + swz(aRow + mi * 16, aSeg)));
#pragma unroll
            for (int mi = 0; mi < 4; mi++)
#pragma unroll
                for (int nj = 0; nj < 4; nj++)
                    mma16816(acc[mi][nj], a[mi],
                             bh[nj >> 1][(nj & 1) * 2], bh[nj >> 1][(nj & 1) * 2 + 1]);
        }
    }

    // epilogue
    const int mbase = m0 + wm * 64;
    const int nbase = n0 + wn * 32;
    float* Cb = Cp + (long)b * sC;
#pragma unroll
    for (int mi = 0; mi < 4; mi++) {
        int mr0 = mbase + mi * 16 + (lane >> 2);
        int mr1 = mr0 + 8;
        bool ok0 = mr0 < MV, ok1 = mr1 < MV;
        float es0 = 1.f, eh0 = 0.f, es1 = 1.f, eh1 = 0.f;
        if (EPI == 1) { if (ok0) eh0 = g_bstk[mr0]; if (ok1) eh1 = g_bstk[mr1]; }
        if (EPI == 2) {
            if (ok0) { es0 = g_escale[mr0]; eh0 = g_eshift[mr0]; }
            if (ok1) { es1 = g_escale[mr1]; eh1 = g_eshift[mr1]; }
        }
#pragma unroll
        for (int nj = 0; nj < 4; nj++) {
            int n = nbase + nj * 8 + (lane & 3) * 2;
            if (n >= NB) continue;
            float2 v0 = make_float2(acc[mi][nj][0], acc[mi][nj][1]);
            float2 v1 = make_float2(acc[mi][nj][2], acc[mi][nj][3]);
            if (EPI == 2) {
                int hj = n / WJ, wj0 = n - hj * WJ;
#pragma unroll
                for (int e = 0; e < 2; e++) {
                    int wj = wj0 + e;
                    int vv = ((hj >= HH) ? 2 : 0) + ((wj >= WW) ? 1 : 0);
                    int hl = (hj >= HH) ? hj - HH : hj;
                    int wl = (wj >= WW) ? wj - WW : wj;
                    long base = (((long)(b * 4 + vv) * CC) * HH + hl) * WW + wl;
                    float r0 = ok0 ? xres[base + (long)mr0 * HH * WW] : 0.f;
                    float r1 = ok1 ? xres[base + (long)mr1 * HH * WW] : 0.f;
                    if (e == 0) { v0.x = v0.x * es0 + eh0 + r0; v1.x = v1.x * es1 + eh1 + r1; }
                    else        { v0.y = v0.y * es0 + eh0 + r0; v1.y = v1.y * es1 + eh1 + r1; }
                }
            } else {
                v0.x = v0.x * es0 + eh0; v0.y = v0.y * es0 + eh0;
                v1.x = v1.x * es1 + eh1; v1.y = v1.y * es1 + eh1;
            }
            if (ok0) *(float2*)(Cb + (long)mr0 * ldC + n) = v0;
            if (ok1) *(float2*)(Cb + (long)mr1 * ldC + n) = v1;
        }
    }
}

// ---------------------------------------------------------------------------
// Launch
// ---------------------------------------------------------------------------
extern "C" void kernel_launch(void* const* d_in, const int* in_sizes, int n_in,
                              void* d_out, int out_size) {
    const float* x     = (const float*)d_in[0];
    const float* wt    = (const float*)d_in[1];
    const float* bt    = (const float*)d_in[2];
    const float* wp    = (const float*)d_in[3];
    const float* bp    = (const float*)d_in[4];
    const float* wg    = (const float*)d_in[5];
    const float* bg    = (const float*)d_in[6];
    const float* wW    = (const float*)d_in[7];
    const float* bW    = (const float*)d_in[8];
    const float* gamma = (const float*)d_in[9];
    const float* beta  = (const float*)d_in[10];
    const float* mean  = (const float*)d_in[11];
    const float* var   = (const float*)d_in[12];
    float* out = (float*)d_out;

    float *p_tpg, *p_phi, *p_f, *p_y;
    __nv_bfloat16 *p_xhT, *p_xlT, *p_thh, *p_thl, *p_phh, *p_phl;
    __nv_bfloat16 *p_gph, *p_gpl, *p_ath, *p_atl, *p_yhT, *p_ylT;
    __nv_bfloat16 *p_whi, *p_wlo, *p_wWhi, *p_wWlo;
    cudaGetSymbolAddress((void**)&p_tpg, g_tpg);
    cudaGetSymbolAddress((void**)&p_phi, g_phi);
    cudaGetSymbolAddress((void**)&p_f, g_f);
    cudaGetSymbolAddress((void**)&p_y, g_y);
    cudaGetSymbolAddress((void**)&p_xhT, g_xhT);
    cudaGetSymbolAddress((void**)&p_xlT, g_xlT);
    cudaGetSymbolAddress((void**)&p_thh, g_thh);
    cudaGetSymbolAddress((void**)&p_thl, g_thl);
    cudaGetSymbolAddress((void**)&p_phh, g_phh);
    cudaGetSymbolAddress((void**)&p_phl, g_phl);
    cudaGetSymbolAddress((void**)&p_gph, g_gph);
    cudaGetSymbolAddress((void**)&p_gpl, g_gpl);
    cudaGetSymbolAddress((void**)&p_ath, g_ath);
    cudaGetSymbolAddress((void**)&p_atl, g_atl);
    cudaGetSymbolAddress((void**)&p_yhT, g_yhT);
    cudaGetSymbolAddress((void**)&p_ylT, g_ylT);
    cudaGetSymbolAddress((void**)&p_whi, g_whi);
    cudaGetSymbolAddress((void**)&p_wlo, g_wlo);
    cudaGetSymbolAddress((void**)&p_wWhi, g_wWhi);
    cudaGetSymbolAddress((void**)&p_wWlo, g_wWlo);

    cudaFuncSetAttribute((const void*)mma128_kernel<0>,
                         cudaFuncAttributeMaxDynamicSharedMemorySize, SMEM3);
    cudaFuncSetAttribute((const void*)mma128_kernel<1>,
                         cudaFuncAttributeMaxDynamicSharedMemorySize, SMEM3);
    cudaFuncSetAttribute((const void*)mma128_kernel<2>,
                         cudaFuncAttributeMaxDynamicSharedMemorySize, SMEM3);

    // #1 weight stack+split (needed by GEMM1)
    {
        long total = (long)CTPG * CC;
        wsplit_stack_kernel<<<(unsigned)((total + 255) / 256), 256>>>(wt, wp, wg, bt, bp, bg);
    }
    // #2 fused joint + transpose + split
    {
        dim3 grid((NN + 31) / 32, CC / 32, BSZ);
        tsplitX_kernel<<<grid, dim3(32, 8)>>>(x);
    }
    // #3 BN prep (placed here so GEMM1 is launch #4 for ncu)
    bnprep_kernel<<<(CC + 255) / 256, 256>>>(gamma, beta, mean, var, bW);
    // #4 stacked theta|phi|g conv  (ncu captures this launch)
    {
        mma128_kernel<1><<<dim3((NN + 127) / 128, CTPG / 128, BSZ), 256, SMEM3>>>(
            p_whi, p_wlo, p_xhT, p_xlT, p_tpg, CC, CTPG, NN,
            0L, (long)NN * CC, NN, (long)CTPG * NN, nullptr);
    }
    // #5 W-conv weight split
    wsplitW_kernel<<<(unsigned)(((long)CC * CI + 255) / 256), 256>>>(wW);
    // #6 pool
    {
        int total = BSZ * CI * (MM + MMP);
        pool_kernel<<<(total + 255) / 256, 256>>>();
    }
    // #7 theta slice -> theta^T hi/lo
    {
        dim3 grid((NN + 31) / 32, CI / 32, BSZ);
        tsplit_kernel<<<grid, dim3(32, 8)>>>(p_tpg, p_thh, p_thl, CI, NN, (long)CTPG * NN);
    }
    // #8 phi -> phi^T hi/lo
    {
        dim3 grid((MM + 31) / 32, CI / 32, BSZ);
        tsplit_kernel<<<grid, dim3(32, 8)>>>(p_phi, p_phh, p_phl, CI, MM, (long)CI * MM);
    }
    // #9 f = thetaT @ phiT^T
    {
        mma128_kernel<0><<<dim3((MM + 127) / 128, (NN + 127) / 128, BSZ), 256, SMEM3>>>(
            p_thh, p_thl, p_phh, p_phl, p_f, CI, NN, MM,
            (long)NN * CI, (long)MM * CI, MM, (long)NN * MM, nullptr);
    }
    // #10 softmax -> attn hi/lo padded
    {
        int rows = BSZ * NN;
        softmax_kernel<<<(rows * 32 + 255) / 256, 256>>>();
    }
    // #11 y = g @ attn^T
    {
        mma128_kernel<0><<<dim3((NN + 127) / 128, CI / 128, BSZ), 256, SMEM3>>>(
            p_gph, p_gpl, p_ath, p_atl, p_y, MMP, CI, NN,
            (long)CI * MMP, (long)NN * MMP, NN, (long)CI * NN, nullptr);
    }
    // #12 y -> y^T hi/lo
    {
        dim3 grid((NN + 31) / 32, CI / 32, BSZ);
        tsplit_kernel<<<grid, dim3(32, 8)>>>(p_y, p_yhT, p_ylT, CI, NN, (long)CI * NN);
    }
    // #13 W conv (3-pass split) + BN + residual -> out
    {
        mma128_kernel<2><<<dim3((NN + 127) / 128, CC / 128, BSZ), 256, SMEM3>>>(
            p_wWhi, p_wWlo, p_yhT, p_ylT, out, CI, CC, NN,
            0L, (long)NN * CI, NN, (long)CC * NN, x);
    }
}